// round 2
// baseline (speedup 1.0000x reference)
#include <cuda_runtime.h>
#include <math_constants.h>

#define N_NODES 100000
#define N_EDGES 1600000
#define N_GRAPHS 64
#define EPSV 1e-16f

// ---------------- scratch (device globals; no allocations) ----------------
__device__ float g_q1[N_NODES * 64];
__device__ float g_k1[N_NODES * 64];
__device__ float g_v1[N_NODES * 64];
__device__ float g_s1[N_NODES * 64];
__device__ float g_acc1[N_NODES * 64];
__device__ float g_h1[N_NODES * 64];

__device__ float g_q2[N_NODES * 128];
__device__ float g_k2[N_NODES * 128];
__device__ float g_v2[N_NODES * 128];
__device__ float g_s2[N_NODES * 128];
__device__ float g_acc2[N_NODES * 128];

__device__ float g_logit[N_EDGES * 2];
__device__ float g_max[N_NODES * 2];
__device__ float g_sum[N_NODES * 2];
__device__ float g_pool[N_GRAPHS * 128];

// ---------------- helpers ----------------
__device__ __forceinline__ void atomicMaxF(float* addr, float val) {
    // signed max for val>=0, unsigned min for val<0 : monotone toward float max
    if (val >= 0.0f)
        atomicMax((int*)addr, __float_as_int(val));
    else
        atomicMin((unsigned int*)addr, __float_as_uint(val));
}

// ---------------- layer 1: node QKV + skip + inits ----------------
__global__ void k_l1_qkv(const float* __restrict__ x,
                         const float* __restrict__ Wq, const float* __restrict__ bq,
                         const float* __restrict__ Wk, const float* __restrict__ bk,
                         const float* __restrict__ Wv, const float* __restrict__ bv,
                         const float* __restrict__ Ws, const float* __restrict__ bs) {
    int idx = blockIdx.x * blockDim.x + threadIdx.x;
    if (idx >= N_NODES * 64) return;
    int n = idx >> 6;
    int j = idx & 63;
    float x0 = __ldg(x + n * 3 + 0);
    float x1 = __ldg(x + n * 3 + 1);
    float x2 = __ldg(x + n * 3 + 2);

    float q = __ldg(bq + j) + x0 * __ldg(Wq + j) + x1 * __ldg(Wq + 64 + j) + x2 * __ldg(Wq + 128 + j);
    float k = __ldg(bk + j) + x0 * __ldg(Wk + j) + x1 * __ldg(Wk + 64 + j) + x2 * __ldg(Wk + 128 + j);
    float v = __ldg(bv + j) + x0 * __ldg(Wv + j) + x1 * __ldg(Wv + 64 + j) + x2 * __ldg(Wv + 128 + j);
    float s = __ldg(bs + j) + x0 * __ldg(Ws + j) + x1 * __ldg(Ws + 64 + j) + x2 * __ldg(Ws + 128 + j);

    g_q1[idx] = q; g_k1[idx] = k; g_v1[idx] = v; g_s1[idx] = s;
    g_acc1[idx] = 0.0f;
    if (j < 2) { g_max[n * 2 + j] = -CUDART_INF_F; g_sum[n * 2 + j] = 0.0f; }
}

// ---------------- edge pass 1: logits + segment max (warp per edge) -------
// L==1: HD=64 (D=32), L==2: HD=128 (D=64). heads=2, q/k layout [n, H*D].
template <int L>
__global__ void k_edge_logits(const int* __restrict__ ei) {
    constexpr int HD = (L == 1) ? 64 : 128;
    constexpr float RSC = (L == 1) ? 0.17677669529663687f : 0.125f;  // 1/sqrt(D)
    const float* __restrict__ q = (L == 1) ? g_q1 : g_q2;
    const float* __restrict__ k = (L == 1) ? g_k1 : g_k2;

    int gw = (blockIdx.x * blockDim.x + threadIdx.x) >> 5;
    int lane = threadIdx.x & 31;
    if (gw >= N_EDGES) return;
    int s = __ldg(ei + gw);
    int d = __ldg(ei + N_EDGES + gw);

    float p;
    if (HD == 128) {
        float4 qa = *(const float4*)(q + (size_t)d * 128 + lane * 4);
        float4 ka = *(const float4*)(k + (size_t)s * 128 + lane * 4);
        p = qa.x * ka.x + qa.y * ka.y + qa.z * ka.z + qa.w * ka.w;
    } else {
        float2 qa = *(const float2*)(q + (size_t)d * 64 + lane * 2);
        float2 ka = *(const float2*)(k + (size_t)s * 64 + lane * 2);
        p = qa.x * ka.x + qa.y * ka.y;
    }
    // lanes 0..15 cover head 0, lanes 16..31 head 1 -> reduce within 16-groups
    p += __shfl_xor_sync(0xFFFFFFFFu, p, 8);
    p += __shfl_xor_sync(0xFFFFFFFFu, p, 4);
    p += __shfl_xor_sync(0xFFFFFFFFu, p, 2);
    p += __shfl_xor_sync(0xFFFFFFFFu, p, 1);
    float p1 = __shfl_sync(0xFFFFFFFFu, p, 16);
    if (lane == 0) {
        float l0 = p * RSC, l1 = p1 * RSC;
        g_logit[(size_t)gw * 2 + 0] = l0;
        g_logit[(size_t)gw * 2 + 1] = l1;
        atomicMaxF(&g_max[d * 2 + 0], l0);
        atomicMaxF(&g_max[d * 2 + 1], l1);
    }
}

// ---------------- edge pass 2: exp + segment sum + weighted scatter -------
template <int L>
__global__ void k_edge_agg(const int* __restrict__ ei) {
    constexpr int HD = (L == 1) ? 64 : 128;
    const float* __restrict__ v = (L == 1) ? g_v1 : g_v2;
    float* __restrict__ acc = (L == 1) ? g_acc1 : g_acc2;

    int gw = (blockIdx.x * blockDim.x + threadIdx.x) >> 5;
    int lane = threadIdx.x & 31;
    if (gw >= N_EDGES) return;
    int s = __ldg(ei + gw);
    int d = __ldg(ei + N_EDGES + gw);

    float l0 = __ldg(&g_logit[(size_t)gw * 2 + 0]);
    float l1 = __ldg(&g_logit[(size_t)gw * 2 + 1]);
    float m0 = __ldg(&g_max[d * 2 + 0]);
    float m1 = __ldg(&g_max[d * 2 + 1]);
    float e0 = __expf(l0 - m0);
    float e1 = __expf(l1 - m1);

    if (lane == 0) atomicAdd(&g_sum[d * 2 + 0], e0);
    if (lane == 1) atomicAdd(&g_sum[d * 2 + 1], e1);

    float eh = (lane < 16) ? e0 : e1;  // lanes 0..15: head0, 16..31: head1
    if (HD == 128) {
        float4 va = *(const float4*)(v + (size_t)s * 128 + lane * 4);
        float4 r = make_float4(va.x * eh, va.y * eh, va.z * eh, va.w * eh);
        atomicAdd((float4*)(acc + (size_t)d * 128 + lane * 4), r);  // sm_90+ vector RED
    } else {
        float2 va = *(const float2*)(v + (size_t)s * 64 + lane * 2);
        float2 r = make_float2(va.x * eh, va.y * eh);
        atomicAdd((float2*)(acc + (size_t)d * 64 + lane * 2), r);
    }
}

// ---------------- finalize: normalize + skip + relu (+ pool for L2) -------
template <int L>
__global__ void k_finalize(const int* __restrict__ batch) {
    constexpr int HD = (L == 1) ? 64 : 128;
    const float* __restrict__ acc = (L == 1) ? g_acc1 : g_acc2;
    const float* __restrict__ skip = (L == 1) ? g_s1 : g_s2;

    int idx = blockIdx.x * blockDim.x + threadIdx.x;
    if (idx >= N_NODES * HD) return;
    int n = idx / HD;
    int j = idx - n * HD;
    int h = (j * 2) / HD;
    float ssum = g_sum[n * 2 + h];
    float val = acc[idx] / (ssum + EPSV) + skip[idx];
    val = fmaxf(val, 0.0f);
    if (L == 1) {
        g_h1[idx] = val;
    } else {
        int g = __ldg(batch + n);
        atomicMaxF(&g_pool[g * 128 + j], val);
    }
}

// ---------------- layer 2: node QKV + skip (register-blocked GEMM) --------
// grid: (N_NODES/8, 4 matrices), block: 128 threads (one output column each)
__global__ void k_l2_qkv(const float* __restrict__ Wq, const float* __restrict__ bq,
                         const float* __restrict__ Wk, const float* __restrict__ bk,
                         const float* __restrict__ Wv, const float* __restrict__ bv,
                         const float* __restrict__ Ws, const float* __restrict__ bs) {
    int j = threadIdx.x;        // 0..127
    int mat = blockIdx.y;       // 0..3
    const float* W; const float* B; float* O;
    if (mat == 0)      { W = Wq; B = bq; O = g_q2; }
    else if (mat == 1) { W = Wk; B = bk; O = g_k2; }
    else if (mat == 2) { W = Wv; B = bv; O = g_v2; }
    else               { W = Ws; B = bs; O = g_s2; }

    int nb = blockIdx.x * 8;    // 100000 % 8 == 0
    float a[8];
    float bj = __ldg(B + j);
#pragma unroll
    for (int r = 0; r < 8; r++) a[r] = bj;

    for (int i = 0; i < 64; i++) {
        float w = __ldg(W + i * 128 + j);
#pragma unroll
        for (int r = 0; r < 8; r++)
            a[r] += __ldg(&g_h1[(size_t)(nb + r) * 64 + i]) * w;  // warp-uniform broadcast
    }
#pragma unroll
    for (int r = 0; r < 8; r++) O[(size_t)(nb + r) * 128 + j] = a[r];

    if (mat == 0) {
#pragma unroll
        for (int r = 0; r < 8; r++) g_acc2[(size_t)(nb + r) * 128 + j] = 0.0f;
        if (j < 2) {
#pragma unroll
            for (int r = 0; r < 8; r++) {
                g_max[(nb + r) * 2 + j] = -CUDART_INF_F;
                g_sum[(nb + r) * 2 + j] = 0.0f;
            }
        }
    }
}

// ---------------- pool init ----------------
__global__ void k_init_pool() {
    int i = blockIdx.x * blockDim.x + threadIdx.x;
    if (i < N_GRAPHS * 128) g_pool[i] = -CUDART_INF_F;
}

// ---------------- MLP head (single block) ----------------
__global__ void k_mlp(const float* __restrict__ W1, const float* __restrict__ b1,
                      const float* __restrict__ W2, const float* __restrict__ b2,
                      const float* __restrict__ W3, const float* __restrict__ b3,
                      float* __restrict__ out) {
    __shared__ float s_lat[64 * 32];
    __shared__ float s_h[64 * 128];
    int tid = threadIdx.x;
    // latent = relu(pool @ W1 + b1)  [64,32]
    for (int idx = tid; idx < 64 * 32; idx += blockDim.x) {
        int g = idx >> 5, j = idx & 31;
        float a = __ldg(b1 + j);
        for (int i = 0; i < 128; i++) a += g_pool[g * 128 + i] * __ldg(W1 + i * 32 + j);
        a = fmaxf(a, 0.0f);
        s_lat[idx] = a;
        out[2560 + idx] = a;           // latent second in output
    }
    __syncthreads();
    // h2 = relu(latent @ W2 + b2)  [64,128]
    for (int idx = tid; idx < 64 * 128; idx += blockDim.x) {
        int g = idx >> 7, j = idx & 127;
        float a = __ldg(b2 + j);
        for (int i = 0; i < 32; i++) a += s_lat[g * 32 + i] * __ldg(W2 + i * 128 + j);
        s_h[idx] = fmaxf(a, 0.0f);
    }
    __syncthreads();
    // logits = h2 @ W3 + b3  [64,40]
    for (int idx = tid; idx < 64 * 40; idx += blockDim.x) {
        int g = idx / 40, c = idx - g * 40;
        float a = __ldg(b3 + c);
        for (int i = 0; i < 128; i++) a += s_h[g * 128 + i] * __ldg(W3 + i * 40 + c);
        out[idx] = a;                  // logits first in output
    }
}

// ---------------- launch ----------------
extern "C" void kernel_launch(void* const* d_in, const int* in_sizes, int n_in,
                              void* d_out, int out_size) {
    const float* x     = (const float*)d_in[0];
    const int*   ei    = (const int*)d_in[1];
    const int*   batch = (const int*)d_in[2];
    const float *Wq1 = (const float*)d_in[3],  *bq1 = (const float*)d_in[4];
    const float *Wk1 = (const float*)d_in[5],  *bk1 = (const float*)d_in[6];
    const float *Wv1 = (const float*)d_in[7],  *bv1 = (const float*)d_in[8];
    const float *Ws1 = (const float*)d_in[9],  *bs1 = (const float*)d_in[10];
    const float *Wq2 = (const float*)d_in[11], *bq2 = (const float*)d_in[12];
    const float *Wk2 = (const float*)d_in[13], *bk2 = (const float*)d_in[14];
    const float *Wv2 = (const float*)d_in[15], *bv2 = (const float*)d_in[16];
    const float *Ws2 = (const float*)d_in[17], *bs2 = (const float*)d_in[18];
    const float *W1  = (const float*)d_in[19], *b1  = (const float*)d_in[20];
    const float *W2  = (const float*)d_in[21], *b2  = (const float*)d_in[22];
    const float *W3  = (const float*)d_in[23], *b3  = (const float*)d_in[24];
    float* out = (float*)d_out;

    const int EDGE_BLOCKS = (N_EDGES * 32 + 255) / 256;

    // layer 1
    k_l1_qkv<<<(N_NODES * 64 + 255) / 256, 256>>>(x, Wq1, bq1, Wk1, bk1, Wv1, bv1, Ws1, bs1);
    k_init_pool<<<(N_GRAPHS * 128 + 255) / 256, 256>>>();
    k_edge_logits<1><<<EDGE_BLOCKS, 256>>>(ei);
    k_edge_agg<1><<<EDGE_BLOCKS, 256>>>(ei);
    k_finalize<1><<<(N_NODES * 64 + 255) / 256, 256>>>(batch);

    // layer 2
    k_l2_qkv<<<dim3(N_NODES / 8, 4), 128>>>(Wq2, bq2, Wk2, bk2, Wv2, bv2, Ws2, bs2);
    k_edge_logits<2><<<EDGE_BLOCKS, 256>>>(ei);
    k_edge_agg<2><<<EDGE_BLOCKS, 256>>>(ei);
    k_finalize<2><<<(N_NODES * 128 + 255) / 256, 256>>>(batch);

    // head
    k_mlp<<<1, 256>>>(W1, b1, W2, b2, W3, b3, out);
}

// round 3
// speedup vs baseline: 1.3344x; 1.3344x over previous
#include <cuda_runtime.h>
#include <math_constants.h>

#define N_NODES 100000
#define N_EDGES 1600000
#define N_GRAPHS 64
#define EPSV 1e-16f

// ---------------- scratch (device globals; no allocations) ----------------
__device__ float g_q1[N_NODES * 64];
__device__ float g_k1[N_NODES * 64];
__device__ float g_v1[N_NODES * 64];
__device__ float g_s1[N_NODES * 64];
__device__ float g_acc1[N_NODES * 64];
__device__ float g_h1[N_NODES * 64];

__device__ float g_q2[N_NODES * 128];
__device__ float g_k2[N_NODES * 128];
__device__ float g_v2[N_NODES * 128];
__device__ float g_s2[N_NODES * 128];
__device__ float g_acc2[N_NODES * 128];

__device__ float g_logit[N_EDGES * 2];
__device__ float g_max[N_NODES * 2];
__device__ float g_sum[N_NODES * 2];
__device__ float g_pool[N_GRAPHS * 128];

// ---------------- helpers ----------------
__device__ __forceinline__ void atomicMaxF(float* addr, float val) {
    if (val >= 0.0f)
        atomicMax((int*)addr, __float_as_int(val));
    else
        atomicMin((unsigned int*)addr, __float_as_uint(val));
}

// ---------------- layer 1: node QKV + skip + inits ----------------
__global__ void k_l1_qkv(const float* __restrict__ x,
                         const float* __restrict__ Wq, const float* __restrict__ bq,
                         const float* __restrict__ Wk, const float* __restrict__ bk,
                         const float* __restrict__ Wv, const float* __restrict__ bv,
                         const float* __restrict__ Ws, const float* __restrict__ bs) {
    int idx = blockIdx.x * blockDim.x + threadIdx.x;
    if (idx >= N_NODES * 64) return;
    int n = idx >> 6;
    int j = idx & 63;
    float x0 = __ldg(x + n * 3 + 0);
    float x1 = __ldg(x + n * 3 + 1);
    float x2 = __ldg(x + n * 3 + 2);

    float q = __ldg(bq + j) + x0 * __ldg(Wq + j) + x1 * __ldg(Wq + 64 + j) + x2 * __ldg(Wq + 128 + j);
    float k = __ldg(bk + j) + x0 * __ldg(Wk + j) + x1 * __ldg(Wk + 64 + j) + x2 * __ldg(Wk + 128 + j);
    float v = __ldg(bv + j) + x0 * __ldg(Wv + j) + x1 * __ldg(Wv + 64 + j) + x2 * __ldg(Wv + 128 + j);
    float s = __ldg(bs + j) + x0 * __ldg(Ws + j) + x1 * __ldg(Ws + 64 + j) + x2 * __ldg(Ws + 128 + j);

    g_q1[idx] = q; g_k1[idx] = k; g_v1[idx] = v; g_s1[idx] = s;
    g_acc1[idx] = 0.0f;
    if (j < 2) { g_max[n * 2 + j] = -CUDART_INF_F; g_sum[n * 2 + j] = 0.0f; }
}

// ======== layer-1 edge pass 1: 16 lanes per edge, float4 loads ========
__global__ void k_edge_logits1(const int* __restrict__ ei) {
    const float RSC = 0.17677669529663687f;  // 1/sqrt(32)
    int warp = (blockIdx.x * blockDim.x + threadIdx.x) >> 5;
    int lane = threadIdx.x & 31;
    int half = lane >> 4;          // which edge of the pair
    int hl = lane & 15;            // lane within edge (0..15)
    int e = warp * 2 + half;
    if (e >= N_EDGES) return;      // N_EDGES even -> whole warp uniform

    int s = __ldg(ei + e);
    int d = __ldg(ei + N_EDGES + e);

    float4 qa = *(const float4*)(g_q1 + (size_t)d * 64 + hl * 4);
    float4 ka = *(const float4*)(g_k1 + (size_t)s * 64 + hl * 4);
    float p = qa.x * ka.x + qa.y * ka.y + qa.z * ka.z + qa.w * ka.w;
    // hl 0..7 -> head0, hl 8..15 -> head1; reduce within 8-lane groups
    p += __shfl_xor_sync(0xFFFFFFFFu, p, 4);
    p += __shfl_xor_sync(0xFFFFFFFFu, p, 2);
    p += __shfl_xor_sync(0xFFFFFFFFu, p, 1);
    float other = __shfl_xor_sync(0xFFFFFFFFu, p, 8);  // swap head groups
    if (hl == 0) {
        float l0 = p * RSC, l1 = other * RSC;
        g_logit[(size_t)e * 2 + 0] = l0;
        g_logit[(size_t)e * 2 + 1] = l1;
        atomicMaxF(&g_max[d * 2 + 0], l0);
        atomicMaxF(&g_max[d * 2 + 1], l1);
    }
}

// ======== layer-1 edge pass 2: 16 lanes per edge, float4 RED ========
__global__ void k_edge_agg1(const int* __restrict__ ei) {
    int warp = (blockIdx.x * blockDim.x + threadIdx.x) >> 5;
    int lane = threadIdx.x & 31;
    int half = lane >> 4;
    int hl = lane & 15;
    int e = warp * 2 + half;
    if (e >= N_EDGES) return;

    int s = __ldg(ei + e);
    int d = __ldg(ei + N_EDGES + e);

    int h = hl >> 3;               // 0 for lanes 0..7, 1 for 8..15
    float l = __ldg(&g_logit[(size_t)e * 2 + h]);
    float m = __ldg(&g_max[d * 2 + h]);
    float eh = __expf(l - m);

    if (hl == 0) atomicAdd(&g_sum[d * 2 + 0], eh);
    if (hl == 8) atomicAdd(&g_sum[d * 2 + 1], eh);

    float4 va = *(const float4*)(g_v1 + (size_t)s * 64 + hl * 4);
    float4 r = make_float4(va.x * eh, va.y * eh, va.z * eh, va.w * eh);
    atomicAdd((float4*)(g_acc1 + (size_t)d * 64 + hl * 4), r);
}

// ======== layer-2 edge pass 1: 2 edges per warp (MLP=4 loads/lane) ========
__global__ void k_edge_logits2(const int* __restrict__ ei) {
    const float RSC = 0.125f;  // 1/sqrt(64)
    int warp = (blockIdx.x * blockDim.x + threadIdx.x) >> 5;
    int lane = threadIdx.x & 31;
    int e0 = warp * 2, e1 = e0 + 1;
    if (e0 >= N_EDGES) return;

    int s0 = __ldg(ei + e0),          s1 = __ldg(ei + e1);
    int d0 = __ldg(ei + N_EDGES + e0), d1 = __ldg(ei + N_EDGES + e1);

    float4 qa0 = *(const float4*)(g_q2 + (size_t)d0 * 128 + lane * 4);
    float4 ka0 = *(const float4*)(g_k2 + (size_t)s0 * 128 + lane * 4);
    float4 qa1 = *(const float4*)(g_q2 + (size_t)d1 * 128 + lane * 4);
    float4 ka1 = *(const float4*)(g_k2 + (size_t)s1 * 128 + lane * 4);
    float p0 = qa0.x * ka0.x + qa0.y * ka0.y + qa0.z * ka0.z + qa0.w * ka0.w;
    float p1 = qa1.x * ka1.x + qa1.y * ka1.y + qa1.z * ka1.z + qa1.w * ka1.w;

    // lanes 0..15 head0, 16..31 head1: reduce within 16-groups
    p0 += __shfl_xor_sync(0xFFFFFFFFu, p0, 8);
    p1 += __shfl_xor_sync(0xFFFFFFFFu, p1, 8);
    p0 += __shfl_xor_sync(0xFFFFFFFFu, p0, 4);
    p1 += __shfl_xor_sync(0xFFFFFFFFu, p1, 4);
    p0 += __shfl_xor_sync(0xFFFFFFFFu, p0, 2);
    p1 += __shfl_xor_sync(0xFFFFFFFFu, p1, 2);
    p0 += __shfl_xor_sync(0xFFFFFFFFu, p0, 1);
    p1 += __shfl_xor_sync(0xFFFFFFFFu, p1, 1);
    float p0h1 = __shfl_sync(0xFFFFFFFFu, p0, 16);
    float p1h1 = __shfl_sync(0xFFFFFFFFu, p1, 16);
    if (lane == 0) {
        float a0 = p0 * RSC, a1 = p0h1 * RSC;
        float b0 = p1 * RSC, b1 = p1h1 * RSC;
        g_logit[(size_t)e0 * 2 + 0] = a0;
        g_logit[(size_t)e0 * 2 + 1] = a1;
        g_logit[(size_t)e1 * 2 + 0] = b0;
        g_logit[(size_t)e1 * 2 + 1] = b1;
        atomicMaxF(&g_max[d0 * 2 + 0], a0);
        atomicMaxF(&g_max[d0 * 2 + 1], a1);
        atomicMaxF(&g_max[d1 * 2 + 0], b0);
        atomicMaxF(&g_max[d1 * 2 + 1], b1);
    }
}

// ======== layer-2 edge pass 2: 2 edges per warp ========
__global__ void k_edge_agg2(const int* __restrict__ ei) {
    int warp = (blockIdx.x * blockDim.x + threadIdx.x) >> 5;
    int lane = threadIdx.x & 31;
    int e0 = warp * 2, e1 = e0 + 1;
    if (e0 >= N_EDGES) return;

    int s0 = __ldg(ei + e0),          s1 = __ldg(ei + e1);
    int d0 = __ldg(ei + N_EDGES + e0), d1 = __ldg(ei + N_EDGES + e1);

    float ex00 = __expf(__ldg(&g_logit[(size_t)e0 * 2 + 0]) - __ldg(&g_max[d0 * 2 + 0]));
    float ex01 = __expf(__ldg(&g_logit[(size_t)e0 * 2 + 1]) - __ldg(&g_max[d0 * 2 + 1]));
    float ex10 = __expf(__ldg(&g_logit[(size_t)e1 * 2 + 0]) - __ldg(&g_max[d1 * 2 + 0]));
    float ex11 = __expf(__ldg(&g_logit[(size_t)e1 * 2 + 1]) - __ldg(&g_max[d1 * 2 + 1]));

    if (lane == 0) atomicAdd(&g_sum[d0 * 2 + 0], ex00);
    if (lane == 1) atomicAdd(&g_sum[d0 * 2 + 1], ex01);
    if (lane == 2) atomicAdd(&g_sum[d1 * 2 + 0], ex10);
    if (lane == 3) atomicAdd(&g_sum[d1 * 2 + 1], ex11);

    float eh0 = (lane < 16) ? ex00 : ex01;
    float eh1 = (lane < 16) ? ex10 : ex11;

    float4 va0 = *(const float4*)(g_v2 + (size_t)s0 * 128 + lane * 4);
    float4 va1 = *(const float4*)(g_v2 + (size_t)s1 * 128 + lane * 4);
    float4 r0 = make_float4(va0.x * eh0, va0.y * eh0, va0.z * eh0, va0.w * eh0);
    float4 r1 = make_float4(va1.x * eh1, va1.y * eh1, va1.z * eh1, va1.w * eh1);
    atomicAdd((float4*)(g_acc2 + (size_t)d0 * 128 + lane * 4), r0);
    atomicAdd((float4*)(g_acc2 + (size_t)d1 * 128 + lane * 4), r1);
}

// ---------------- finalize layer 1: normalize + skip + relu ----------------
__global__ void k_finalize1() {
    int idx = blockIdx.x * blockDim.x + threadIdx.x;
    if (idx >= N_NODES * 64) return;
    int n = idx >> 6;
    int j = idx & 63;
    int h = j >> 5;
    float ssum = g_sum[n * 2 + h];
    float val = g_acc1[idx] / (ssum + EPSV) + g_s1[idx];
    g_h1[idx] = fmaxf(val, 0.0f);
}

// ---------------- finalize layer 2: normalize+skip+relu+pool (32 nodes/block)
__global__ void k_finalize2(const int* __restrict__ batch) {
    int j = threadIdx.x;              // 0..127 (column)
    int n0 = blockIdx.x * 32;         // 100000 / 32 = 3125 blocks
    int h = j >> 6;
    float cur = -CUDART_INF_F;
    int curg = __ldg(batch + n0);
#pragma unroll 4
    for (int r = 0; r < 32; r++) {
        int n = n0 + r;
        int g = __ldg(batch + n);
        if (g != curg) {
            atomicMaxF(&g_pool[curg * 128 + j], cur);
            cur = -CUDART_INF_F;
            curg = g;
        }
        float ssum = g_sum[n * 2 + h];
        float val = g_acc2[(size_t)n * 128 + j] / (ssum + EPSV) + g_s2[(size_t)n * 128 + j];
        cur = fmaxf(cur, fmaxf(val, 0.0f));
    }
    atomicMaxF(&g_pool[curg * 128 + j], cur);
}

// ---------------- layer 2: node QKV + skip (register-blocked GEMM) --------
__global__ void k_l2_qkv(const float* __restrict__ Wq, const float* __restrict__ bq,
                         const float* __restrict__ Wk, const float* __restrict__ bk,
                         const float* __restrict__ Wv, const float* __restrict__ bv,
                         const float* __restrict__ Ws, const float* __restrict__ bs) {
    int j = threadIdx.x;        // 0..127
    int mat = blockIdx.y;       // 0..3
    const float* W; const float* B; float* O;
    if (mat == 0)      { W = Wq; B = bq; O = g_q2; }
    else if (mat == 1) { W = Wk; B = bk; O = g_k2; }
    else if (mat == 2) { W = Wv; B = bv; O = g_v2; }
    else               { W = Ws; B = bs; O = g_s2; }

    int nb = blockIdx.x * 8;    // 100000 % 8 == 0
    float a[8];
    float bj = __ldg(B + j);
#pragma unroll
    for (int r = 0; r < 8; r++) a[r] = bj;

    for (int i = 0; i < 64; i++) {
        float w = __ldg(W + i * 128 + j);
#pragma unroll
        for (int r = 0; r < 8; r++)
            a[r] += __ldg(&g_h1[(size_t)(nb + r) * 64 + i]) * w;  // warp-uniform broadcast
    }
#pragma unroll
    for (int r = 0; r < 8; r++) O[(size_t)(nb + r) * 128 + j] = a[r];

    if (mat == 0) {
#pragma unroll
        for (int r = 0; r < 8; r++) g_acc2[(size_t)(nb + r) * 128 + j] = 0.0f;
        if (j < 2) {
#pragma unroll
            for (int r = 0; r < 8; r++) {
                g_max[(nb + r) * 2 + j] = -CUDART_INF_F;
                g_sum[(nb + r) * 2 + j] = 0.0f;
            }
        }
    }
}

// ---------------- pool init ----------------
__global__ void k_init_pool() {
    int i = blockIdx.x * blockDim.x + threadIdx.x;
    if (i < N_GRAPHS * 128) g_pool[i] = -CUDART_INF_F;
}

// ---------------- MLP head (single block) ----------------
__global__ void k_mlp(const float* __restrict__ W1, const float* __restrict__ b1,
                      const float* __restrict__ W2, const float* __restrict__ b2,
                      const float* __restrict__ W3, const float* __restrict__ b3,
                      float* __restrict__ out) {
    __shared__ float s_lat[64 * 32];
    __shared__ float s_h[64 * 128];
    int tid = threadIdx.x;
    for (int idx = tid; idx < 64 * 32; idx += blockDim.x) {
        int g = idx >> 5, j = idx & 31;
        float a = __ldg(b1 + j);
        for (int i = 0; i < 128; i++) a += g_pool[g * 128 + i] * __ldg(W1 + i * 32 + j);
        a = fmaxf(a, 0.0f);
        s_lat[idx] = a;
        out[2560 + idx] = a;           // latent second in output
    }
    __syncthreads();
    for (int idx = tid; idx < 64 * 128; idx += blockDim.x) {
        int g = idx >> 7, j = idx & 127;
        float a = __ldg(b2 + j);
        for (int i = 0; i < 32; i++) a += s_lat[g * 32 + i] * __ldg(W2 + i * 128 + j);
        s_h[idx] = fmaxf(a, 0.0f);
    }
    __syncthreads();
    for (int idx = tid; idx < 64 * 40; idx += blockDim.x) {
        int g = idx / 40, c = idx - g * 40;
        float a = __ldg(b3 + c);
        for (int i = 0; i < 128; i++) a += s_h[g * 128 + i] * __ldg(W3 + i * 40 + c);
        out[idx] = a;                  // logits first in output
    }
}

// ---------------- launch ----------------
extern "C" void kernel_launch(void* const* d_in, const int* in_sizes, int n_in,
                              void* d_out, int out_size) {
    const float* x     = (const float*)d_in[0];
    const int*   ei    = (const int*)d_in[1];
    const int*   batch = (const int*)d_in[2];
    const float *Wq1 = (const float*)d_in[3],  *bq1 = (const float*)d_in[4];
    const float *Wk1 = (const float*)d_in[5],  *bk1 = (const float*)d_in[6];
    const float *Wv1 = (const float*)d_in[7],  *bv1 = (const float*)d_in[8];
    const float *Ws1 = (const float*)d_in[9],  *bs1 = (const float*)d_in[10];
    const float *Wq2 = (const float*)d_in[11], *bq2 = (const float*)d_in[12];
    const float *Wk2 = (const float*)d_in[13], *bk2 = (const float*)d_in[14];
    const float *Wv2 = (const float*)d_in[15], *bv2 = (const float*)d_in[16];
    const float *Ws2 = (const float*)d_in[17], *bs2 = (const float*)d_in[18];
    const float *W1  = (const float*)d_in[19], *b1  = (const float*)d_in[20];
    const float *W2  = (const float*)d_in[21], *b2  = (const float*)d_in[22];
    const float *W3  = (const float*)d_in[23], *b3  = (const float*)d_in[24];
    float* out = (float*)d_out;

    // 2 edges per warp everywhere: N_EDGES/2 warps
    const int PAIR_BLOCKS = ((N_EDGES / 2) * 32 + 255) / 256;

    // layer 1
    k_l1_qkv<<<(N_NODES * 64 + 255) / 256, 256>>>(x, Wq1, bq1, Wk1, bk1, Wv1, bv1, Ws1, bs1);
    k_init_pool<<<(N_GRAPHS * 128 + 255) / 256, 256>>>();
    k_edge_logits1<<<PAIR_BLOCKS, 256>>>(ei);
    k_edge_agg1<<<PAIR_BLOCKS, 256>>>(ei);
    k_finalize1<<<(N_NODES * 64 + 255) / 256, 256>>>();

    // layer 2
    k_l2_qkv<<<dim3(N_NODES / 8, 4), 128>>>(Wq2, bq2, Wk2, bk2, Wv2, bv2, Ws2, bs2);
    k_edge_logits2<<<PAIR_BLOCKS, 256>>>(ei);
    k_edge_agg2<<<PAIR_BLOCKS, 256>>>(ei);
    k_finalize2<<<N_NODES / 32, 128>>>(batch);

    // head
    k_mlp<<<1, 256>>>(W1, b1, W2, b2, W3, b3, out);
}

// round 4
// speedup vs baseline: 1.4190x; 1.0634x over previous
#include <cuda_runtime.h>
#include <math_constants.h>

#define N_NODES 100000
#define N_EDGES 1600000
#define N_GRAPHS 64
#define EPSV 1e-16f

// ---------------- scratch (device globals; no allocations) ----------------
__device__ float g_q1[N_NODES * 64];
__device__ float g_k1[N_NODES * 64];
__device__ float g_v1[N_NODES * 64];
__device__ float g_s1[N_NODES * 64];
__device__ float g_h1[N_NODES * 64];

__device__ float g_q2[N_NODES * 128];   // after layer-2 E2, reused to hold h2
__device__ float g_k2[N_NODES * 128];
__device__ float g_v2[N_NODES * 128];
__device__ float g_s2[N_NODES * 128];

__device__ float2 g_logit[N_EDGES];     // CSR-ordered (l_head0, l_head1)
__device__ float4 g_msum[N_NODES];      // (m0, m1, s0, s1)
__device__ float  g_pool[N_GRAPHS * 128];

// CSR
__device__ int g_deg[N_NODES];
__device__ int g_rowptr[N_NODES + 1];
__device__ int g_cursor[N_NODES];
__device__ int g_esrc[N_EDGES];

// ---------------- helpers ----------------
__device__ __forceinline__ void atomicMaxF(float* addr, float val) {
    if (val >= 0.0f)
        atomicMax((int*)addr, __float_as_int(val));
    else
        atomicMin((unsigned int*)addr, __float_as_uint(val));
}

// ================= CSR build =================
__global__ void k_zero_deg() {
    int i = blockIdx.x * blockDim.x + threadIdx.x;
    if (i < N_NODES) g_deg[i] = 0;
}

__global__ void k_hist(const int* __restrict__ ei) {
    int e = blockIdx.x * blockDim.x + threadIdx.x;
    if (e < N_EDGES) atomicAdd(&g_deg[__ldg(ei + N_EDGES + e)], 1);
}

// single-block exclusive scan over 100k degrees -> rowptr + cursor
__global__ void k_scan() {
    __shared__ int s_sums[1024];
    const int CH = 98;                       // 1024*98 >= 100000
    int t = threadIdx.x;
    int base = t * CH;
    int sum = 0;
    for (int i = 0; i < CH; i++) {
        int idx = base + i;
        if (idx < N_NODES) sum += g_deg[idx];
    }
    s_sums[t] = sum;
    __syncthreads();
    // inclusive Hillis-Steele
    for (int d = 1; d < 1024; d <<= 1) {
        int v = (t >= d) ? s_sums[t - d] : 0;
        __syncthreads();
        s_sums[t] += v;
        __syncthreads();
    }
    int run = s_sums[t] - sum;               // exclusive offset for this chunk
    for (int i = 0; i < CH; i++) {
        int idx = base + i;
        if (idx < N_NODES) {
            g_rowptr[idx] = run;
            g_cursor[idx] = run;
            run += g_deg[idx];
        }
    }
    if (t == 1023) g_rowptr[N_NODES] = N_EDGES;
}

__global__ void k_scatter(const int* __restrict__ ei) {
    int e = blockIdx.x * blockDim.x + threadIdx.x;
    if (e >= N_EDGES) return;
    int s = __ldg(ei + e);
    int d = __ldg(ei + N_EDGES + e);
    int pos = atomicAdd(&g_cursor[d], 1);
    g_esrc[pos] = s;
}

// ---------------- layer 1: node QKV + skip ----------------
__global__ void k_l1_qkv(const float* __restrict__ x,
                         const float* __restrict__ Wq, const float* __restrict__ bq,
                         const float* __restrict__ Wk, const float* __restrict__ bk,
                         const float* __restrict__ Wv, const float* __restrict__ bv,
                         const float* __restrict__ Ws, const float* __restrict__ bs) {
    int idx = blockIdx.x * blockDim.x + threadIdx.x;
    if (idx >= N_NODES * 64) return;
    int n = idx >> 6;
    int j = idx & 63;
    float x0 = __ldg(x + n * 3 + 0);
    float x1 = __ldg(x + n * 3 + 1);
    float x2 = __ldg(x + n * 3 + 2);

    g_q1[idx] = __ldg(bq + j) + x0 * __ldg(Wq + j) + x1 * __ldg(Wq + 64 + j) + x2 * __ldg(Wq + 128 + j);
    g_k1[idx] = __ldg(bk + j) + x0 * __ldg(Wk + j) + x1 * __ldg(Wk + 64 + j) + x2 * __ldg(Wk + 128 + j);
    g_v1[idx] = __ldg(bv + j) + x0 * __ldg(Wv + j) + x1 * __ldg(Wv + 64 + j) + x2 * __ldg(Wv + 128 + j);
    g_s1[idx] = __ldg(bs + j) + x0 * __ldg(Ws + j) + x1 * __ldg(Ws + 64 + j) + x2 * __ldg(Ws + 128 + j);
}

// ================= E1: logits + segment max + sum (warp per dst node) ======
// L==1: HD=64 (float2/lane), L==2: HD=128 (float4/lane). heads=2.
template <int L>
__global__ void k_e1() {
    constexpr float RSC = (L == 1) ? 0.17677669529663687f : 0.125f;
    const float* __restrict__ q = (L == 1) ? g_q1 : g_q2;
    const float* __restrict__ k = (L == 1) ? g_k1 : g_k2;

    int n = (blockIdx.x * blockDim.x + threadIdx.x) >> 5;
    int lane = threadIdx.x & 31;
    if (n >= N_NODES) return;

    int beg = __ldg(&g_rowptr[n]);
    int end = __ldg(&g_rowptr[n + 1]);

    // load q row once per node
    float4 qa4; float2 qa2;
    if (L == 2) qa4 = *(const float4*)(q + (size_t)n * 128 + lane * 4);
    else        qa2 = *(const float2*)(q + (size_t)n * 64 + lane * 2);

    float m0 = -CUDART_INF_F, m1 = -CUDART_INF_F;
    for (int idx = beg; idx < end; idx++) {
        int src = __ldg(&g_esrc[idx]);     // uniform
        float p;
        if (L == 2) {
            float4 ka = *(const float4*)(k + (size_t)src * 128 + lane * 4);
            p = qa4.x * ka.x + qa4.y * ka.y + qa4.z * ka.z + qa4.w * ka.w;
        } else {
            float2 ka = *(const float2*)(k + (size_t)src * 64 + lane * 2);
            p = qa2.x * ka.x + qa2.y * ka.y;
        }
        // lanes 0..15 cover head 0, lanes 16..31 head 1
        p += __shfl_xor_sync(0xFFFFFFFFu, p, 8);
        p += __shfl_xor_sync(0xFFFFFFFFu, p, 4);
        p += __shfl_xor_sync(0xFFFFFFFFu, p, 2);
        p += __shfl_xor_sync(0xFFFFFFFFu, p, 1);
        float l0 = __shfl_sync(0xFFFFFFFFu, p, 0) * RSC;
        float l1 = __shfl_sync(0xFFFFFFFFu, p, 16) * RSC;
        if (lane == 0) g_logit[idx] = make_float2(l0, l1);
        m0 = fmaxf(m0, l0);
        m1 = fmaxf(m1, l1);
    }

    // sums (coalesced re-read of just-written logits; L2-hot)
    float s0 = 0.0f, s1 = 0.0f;
    for (int base = beg; base < end; base += 32) {
        int idx = base + lane;
        if (idx < end) {
            float2 l = g_logit[idx];
            s0 += __expf(l.x - m0);
            s1 += __expf(l.y - m1);
        }
    }
#pragma unroll
    for (int d = 16; d >= 1; d >>= 1) {
        s0 += __shfl_xor_sync(0xFFFFFFFFu, s0, d);
        s1 += __shfl_xor_sync(0xFFFFFFFFu, s1, d);
    }
    if (lane == 0) g_msum[n] = make_float4(m0, m1, s0, s1);
}

// ================= E2: weighted gather + normalize + skip + relu ===========
template <int L>
__global__ void k_e2() {
    const float* __restrict__ v    = (L == 1) ? g_v1 : g_v2;
    const float* __restrict__ skip = (L == 1) ? g_s1 : g_s2;
    float* __restrict__ outp       = (L == 1) ? g_h1 : g_q2;   // q2 reused as h2

    int n = (blockIdx.x * blockDim.x + threadIdx.x) >> 5;
    int lane = threadIdx.x & 31;
    if (n >= N_NODES) return;

    int beg = __ldg(&g_rowptr[n]);
    int end = __ldg(&g_rowptr[n + 1]);

    float4 ms = g_msum[n];
    int h = lane >> 4;                       // head of this lane's columns
    float mh = h ? ms.y : ms.x;
    float rh = 1.0f / ((h ? ms.w : ms.z) + EPSV);

    if (L == 2) {
        float4 acc = make_float4(0.f, 0.f, 0.f, 0.f);
        for (int idx = beg; idx < end; idx++) {
            int src = __ldg(&g_esrc[idx]);
            float2 l = g_logit[idx];         // uniform
            float eh = __expf((h ? l.y : l.x) - mh);
            float4 va = *(const float4*)(v + (size_t)src * 128 + lane * 4);
            acc.x += eh * va.x; acc.y += eh * va.y;
            acc.z += eh * va.z; acc.w += eh * va.w;
        }
        float4 sk = *(const float4*)(skip + (size_t)n * 128 + lane * 4);
        float4 o;
        o.x = fmaxf(acc.x * rh + sk.x, 0.0f);
        o.y = fmaxf(acc.y * rh + sk.y, 0.0f);
        o.z = fmaxf(acc.z * rh + sk.z, 0.0f);
        o.w = fmaxf(acc.w * rh + sk.w, 0.0f);
        *(float4*)(outp + (size_t)n * 128 + lane * 4) = o;
    } else {
        float2 acc = make_float2(0.f, 0.f);
        for (int idx = beg; idx < end; idx++) {
            int src = __ldg(&g_esrc[idx]);
            float2 l = g_logit[idx];
            float eh = __expf((h ? l.y : l.x) - mh);
            float2 va = *(const float2*)(v + (size_t)src * 64 + lane * 2);
            acc.x += eh * va.x; acc.y += eh * va.y;
        }
        float2 sk = *(const float2*)(skip + (size_t)n * 64 + lane * 2);
        float2 o;
        o.x = fmaxf(acc.x * rh + sk.x, 0.0f);
        o.y = fmaxf(acc.y * rh + sk.y, 0.0f);
        *(float2*)(outp + (size_t)n * 64 + lane * 2) = o;
    }
}

// ---------------- layer 2: node QKV + skip (register-blocked GEMM) --------
__global__ void k_l2_qkv(const float* __restrict__ Wq, const float* __restrict__ bq,
                         const float* __restrict__ Wk, const float* __restrict__ bk,
                         const float* __restrict__ Wv, const float* __restrict__ bv,
                         const float* __restrict__ Ws, const float* __restrict__ bs) {
    int j = threadIdx.x;        // 0..127
    int mat = blockIdx.y;       // 0..3
    const float* W; const float* B; float* O;
    if (mat == 0)      { W = Wq; B = bq; O = g_q2; }
    else if (mat == 1) { W = Wk; B = bk; O = g_k2; }
    else if (mat == 2) { W = Wv; B = bv; O = g_v2; }
    else               { W = Ws; B = bs; O = g_s2; }

    int nb = blockIdx.x * 8;    // 100000 % 8 == 0
    float a[8];
    float bj = __ldg(B + j);
#pragma unroll
    for (int r = 0; r < 8; r++) a[r] = bj;

    for (int i = 0; i < 64; i++) {
        float w = __ldg(W + i * 128 + j);
#pragma unroll
        for (int r = 0; r < 8; r++)
            a[r] += __ldg(&g_h1[(size_t)(nb + r) * 64 + i]) * w;
    }
#pragma unroll
    for (int r = 0; r < 8; r++) O[(size_t)(nb + r) * 128 + j] = a[r];
}

// ---------------- pool init ----------------
__global__ void k_init_pool() {
    int i = blockIdx.x * blockDim.x + threadIdx.x;
    if (i < N_GRAPHS * 128) g_pool[i] = -CUDART_INF_F;
}

// ---------------- pool: run-length max over sorted batch (32 nodes/block) --
__global__ void k_pool(const int* __restrict__ batch) {
    int j = threadIdx.x;              // 0..127 (column)
    int n0 = blockIdx.x * 32;         // 100000 / 32 = 3125 blocks
    float cur = -CUDART_INF_F;
    int curg = __ldg(batch + n0);
#pragma unroll 4
    for (int r = 0; r < 32; r++) {
        int n = n0 + r;
        int g = __ldg(batch + n);
        if (g != curg) {
            atomicMaxF(&g_pool[curg * 128 + j], cur);
            cur = -CUDART_INF_F;
            curg = g;
        }
        cur = fmaxf(cur, g_q2[(size_t)n * 128 + j]);   // h2 lives in g_q2
    }
    atomicMaxF(&g_pool[curg * 128 + j], cur);
}

// ---------------- MLP head (single block) ----------------
__global__ void k_mlp(const float* __restrict__ W1, const float* __restrict__ b1,
                      const float* __restrict__ W2, const float* __restrict__ b2,
                      const float* __restrict__ W3, const float* __restrict__ b3,
                      float* __restrict__ out) {
    __shared__ float s_lat[64 * 32];
    __shared__ float s_h[64 * 128];
    int tid = threadIdx.x;
    for (int idx = tid; idx < 64 * 32; idx += blockDim.x) {
        int g = idx >> 5, j = idx & 31;
        float a = __ldg(b1 + j);
        for (int i = 0; i < 128; i++) a += g_pool[g * 128 + i] * __ldg(W1 + i * 32 + j);
        a = fmaxf(a, 0.0f);
        s_lat[idx] = a;
        out[2560 + idx] = a;           // latent second in output
    }
    __syncthreads();
    for (int idx = tid; idx < 64 * 128; idx += blockDim.x) {
        int g = idx >> 7, j = idx & 127;
        float a = __ldg(b2 + j);
        for (int i = 0; i < 32; i++) a += s_lat[g * 32 + i] * __ldg(W2 + i * 128 + j);
        s_h[idx] = fmaxf(a, 0.0f);
    }
    __syncthreads();
    for (int idx = tid; idx < 64 * 40; idx += blockDim.x) {
        int g = idx / 40, c = idx - g * 40;
        float a = __ldg(b3 + c);
        for (int i = 0; i < 128; i++) a += s_h[g * 128 + i] * __ldg(W3 + i * 40 + c);
        out[idx] = a;                  // logits first in output
    }
}

// ---------------- launch ----------------
extern "C" void kernel_launch(void* const* d_in, const int* in_sizes, int n_in,
                              void* d_out, int out_size) {
    const float* x     = (const float*)d_in[0];
    const int*   ei    = (const int*)d_in[1];
    const int*   batch = (const int*)d_in[2];
    const float *Wq1 = (const float*)d_in[3],  *bq1 = (const float*)d_in[4];
    const float *Wk1 = (const float*)d_in[5],  *bk1 = (const float*)d_in[6];
    const float *Wv1 = (const float*)d_in[7],  *bv1 = (const float*)d_in[8];
    const float *Ws1 = (const float*)d_in[9],  *bs1 = (const float*)d_in[10];
    const float *Wq2 = (const float*)d_in[11], *bq2 = (const float*)d_in[12];
    const float *Wk2 = (const float*)d_in[13], *bk2 = (const float*)d_in[14];
    const float *Wv2 = (const float*)d_in[15], *bv2 = (const float*)d_in[16];
    const float *Ws2 = (const float*)d_in[17], *bs2 = (const float*)d_in[18];
    const float *W1  = (const float*)d_in[19], *b1  = (const float*)d_in[20];
    const float *W2  = (const float*)d_in[21], *b2  = (const float*)d_in[22];
    const float *W3  = (const float*)d_in[23], *b3  = (const float*)d_in[24];
    float* out = (float*)d_out;

    const int NODE_WARP_BLOCKS = (N_NODES * 32 + 255) / 256;

    // CSR build (once; reused by both layers)
    k_zero_deg<<<(N_NODES + 255) / 256, 256>>>();
    k_hist<<<(N_EDGES + 255) / 256, 256>>>(ei);
    k_scan<<<1, 1024>>>();
    k_scatter<<<(N_EDGES + 255) / 256, 256>>>(ei);

    // layer 1
    k_l1_qkv<<<(N_NODES * 64 + 255) / 256, 256>>>(x, Wq1, bq1, Wk1, bk1, Wv1, bv1, Ws1, bs1);
    k_init_pool<<<(N_GRAPHS * 128 + 255) / 256, 256>>>();
    k_e1<1><<<NODE_WARP_BLOCKS, 256>>>();
    k_e2<1><<<NODE_WARP_BLOCKS, 256>>>();

    // layer 2
    k_l2_qkv<<<dim3(N_NODES / 8, 4), 128>>>(Wq2, bq2, Wk2, bk2, Wv2, bv2, Ws2, bs2);
    k_e1<2><<<NODE_WARP_BLOCKS, 256>>>();
    k_e2<2><<<NODE_WARP_BLOCKS, 256>>>();
    k_pool<<<N_NODES / 32, 128>>>(batch);

    // head
    k_mlp<<<1, 256>>>(W1, b1, W2, b2, W3, b3, out);
}

// round 5
// speedup vs baseline: 1.4632x; 1.0312x over previous
#include <cuda_runtime.h>
#include <math_constants.h>

#define N_NODES 100000
#define N_EDGES 1600000
#define N_GRAPHS 64
#define EPSV 1e-16f

// ---------------- scratch (device globals; no allocations) ----------------
__device__ float g_q1[N_NODES * 64];
__device__ float g_k1[N_NODES * 64];
__device__ float g_v1[N_NODES * 64];
__device__ float g_s1[N_NODES * 64];
__device__ float g_h1[N_NODES * 64];

__device__ float g_q2[N_NODES * 128];   // after layer-2 E2, reused to hold h2
__device__ float g_k2[N_NODES * 128];
__device__ float g_v2[N_NODES * 128];
__device__ float g_s2[N_NODES * 128];

__device__ float2 g_logit[N_EDGES];     // CSR-ordered (l_head0, l_head1)
__device__ float4 g_msum[N_NODES];      // (m0, m1, s0, s1)
__device__ float  g_pool[N_GRAPHS * 128];

// CSR
__device__ int g_deg[N_NODES];
__device__ int g_rowptr[N_NODES + 1];
__device__ int g_cursor[N_NODES];
__device__ int g_esrc[N_EDGES];

// ---------------- helpers ----------------
__device__ __forceinline__ void atomicMaxF(float* addr, float val) {
    if (val >= 0.0f)
        atomicMax((int*)addr, __float_as_int(val));
    else
        atomicMin((unsigned int*)addr, __float_as_uint(val));
}

// ================= CSR build =================
__global__ void k_zero_deg() {
    int i = blockIdx.x * blockDim.x + threadIdx.x;
    if (i < N_NODES) g_deg[i] = 0;
}

__global__ void k_hist(const int* __restrict__ ei) {
    int e = blockIdx.x * blockDim.x + threadIdx.x;
    if (e < N_EDGES) atomicAdd(&g_deg[__ldg(ei + N_EDGES + e)], 1);
}

__global__ void k_scan() {
    __shared__ int s_sums[1024];
    const int CH = 98;
    int t = threadIdx.x;
    int base = t * CH;
    int sum = 0;
    for (int i = 0; i < CH; i++) {
        int idx = base + i;
        if (idx < N_NODES) sum += g_deg[idx];
    }
    s_sums[t] = sum;
    __syncthreads();
    for (int d = 1; d < 1024; d <<= 1) {
        int v = (t >= d) ? s_sums[t - d] : 0;
        __syncthreads();
        s_sums[t] += v;
        __syncthreads();
    }
    int run = s_sums[t] - sum;
    for (int i = 0; i < CH; i++) {
        int idx = base + i;
        if (idx < N_NODES) {
            g_rowptr[idx] = run;
            g_cursor[idx] = run;
            run += g_deg[idx];
        }
    }
    if (t == 1023) g_rowptr[N_NODES] = N_EDGES;
}

__global__ void k_scatter(const int* __restrict__ ei) {
    int e = blockIdx.x * blockDim.x + threadIdx.x;
    if (e >= N_EDGES) return;
    int s = __ldg(ei + e);
    int d = __ldg(ei + N_EDGES + e);
    int pos = atomicAdd(&g_cursor[d], 1);
    g_esrc[pos] = s;
}

// ---------------- layer 1: node QKV + skip ----------------
__global__ void k_l1_qkv(const float* __restrict__ x,
                         const float* __restrict__ Wq, const float* __restrict__ bq,
                         const float* __restrict__ Wk, const float* __restrict__ bk,
                         const float* __restrict__ Wv, const float* __restrict__ bv,
                         const float* __restrict__ Ws, const float* __restrict__ bs) {
    int idx = blockIdx.x * blockDim.x + threadIdx.x;
    if (idx >= N_NODES * 64) return;
    int n = idx >> 6;
    int j = idx & 63;
    float x0 = __ldg(x + n * 3 + 0);
    float x1 = __ldg(x + n * 3 + 1);
    float x2 = __ldg(x + n * 3 + 2);

    g_q1[idx] = __ldg(bq + j) + x0 * __ldg(Wq + j) + x1 * __ldg(Wq + 64 + j) + x2 * __ldg(Wq + 128 + j);
    g_k1[idx] = __ldg(bk + j) + x0 * __ldg(Wk + j) + x1 * __ldg(Wk + 64 + j) + x2 * __ldg(Wk + 128 + j);
    g_v1[idx] = __ldg(bv + j) + x0 * __ldg(Wv + j) + x1 * __ldg(Wv + 64 + j) + x2 * __ldg(Wv + 128 + j);
    g_s1[idx] = __ldg(bs + j) + x0 * __ldg(Ws + j) + x1 * __ldg(Ws + 64 + j) + x2 * __ldg(Ws + 128 + j);
}

// ================= E1: logits + segment max + sum (warp per dst node) ======
// 4-edge software pipelining: batch gathers + interleaved shuffle chains.
template <int L>
__global__ void k_e1() {
    constexpr float RSC = (L == 1) ? 0.17677669529663687f : 0.125f;
    const float* __restrict__ q = (L == 1) ? g_q1 : g_q2;
    const float* __restrict__ k = (L == 1) ? g_k1 : g_k2;

    int n = (blockIdx.x * blockDim.x + threadIdx.x) >> 5;
    int lane = threadIdx.x & 31;
    if (n >= N_NODES) return;

    int beg = __ldg(&g_rowptr[n]);
    int end = __ldg(&g_rowptr[n + 1]);

    float4 qa4; float2 qa2;
    if (L == 2) qa4 = *(const float4*)(q + (size_t)n * 128 + lane * 4);
    else        qa2 = *(const float2*)(q + (size_t)n * 64 + lane * 2);

    float m0 = -CUDART_INF_F, m1 = -CUDART_INF_F;

    int idx = beg;
    for (; idx + 4 <= end; idx += 4) {
        int s0 = __ldg(&g_esrc[idx + 0]);
        int s1 = __ldg(&g_esrc[idx + 1]);
        int s2 = __ldg(&g_esrc[idx + 2]);
        int s3 = __ldg(&g_esrc[idx + 3]);

        float p0, p1, p2, p3;
        if (L == 2) {
            float4 k0 = *(const float4*)(k + (size_t)s0 * 128 + lane * 4);
            float4 k1 = *(const float4*)(k + (size_t)s1 * 128 + lane * 4);
            float4 k2 = *(const float4*)(k + (size_t)s2 * 128 + lane * 4);
            float4 k3 = *(const float4*)(k + (size_t)s3 * 128 + lane * 4);
            p0 = qa4.x * k0.x + qa4.y * k0.y + qa4.z * k0.z + qa4.w * k0.w;
            p1 = qa4.x * k1.x + qa4.y * k1.y + qa4.z * k1.z + qa4.w * k1.w;
            p2 = qa4.x * k2.x + qa4.y * k2.y + qa4.z * k2.z + qa4.w * k2.w;
            p3 = qa4.x * k3.x + qa4.y * k3.y + qa4.z * k3.z + qa4.w * k3.w;
        } else {
            float2 k0 = *(const float2*)(k + (size_t)s0 * 64 + lane * 2);
            float2 k1 = *(const float2*)(k + (size_t)s1 * 64 + lane * 2);
            float2 k2 = *(const float2*)(k + (size_t)s2 * 64 + lane * 2);
            float2 k3 = *(const float2*)(k + (size_t)s3 * 64 + lane * 2);
            p0 = qa2.x * k0.x + qa2.y * k0.y;
            p1 = qa2.x * k1.x + qa2.y * k1.y;
            p2 = qa2.x * k2.x + qa2.y * k2.y;
            p3 = qa2.x * k3.x + qa2.y * k3.y;
        }
        // interleaved 16-lane reductions (lanes 0..15 head0, 16..31 head1)
#pragma unroll
        for (int d = 8; d >= 1; d >>= 1) {
            p0 += __shfl_xor_sync(0xFFFFFFFFu, p0, d);
            p1 += __shfl_xor_sync(0xFFFFFFFFu, p1, d);
            p2 += __shfl_xor_sync(0xFFFFFFFFu, p2, d);
            p3 += __shfl_xor_sync(0xFFFFFFFFu, p3, d);
        }
        float a00 = __shfl_sync(0xFFFFFFFFu, p0, 0)  * RSC;
        float a01 = __shfl_sync(0xFFFFFFFFu, p0, 16) * RSC;
        float a10 = __shfl_sync(0xFFFFFFFFu, p1, 0)  * RSC;
        float a11 = __shfl_sync(0xFFFFFFFFu, p1, 16) * RSC;
        float a20 = __shfl_sync(0xFFFFFFFFu, p2, 0)  * RSC;
        float a21 = __shfl_sync(0xFFFFFFFFu, p2, 16) * RSC;
        float a30 = __shfl_sync(0xFFFFFFFFu, p3, 0)  * RSC;
        float a31 = __shfl_sync(0xFFFFFFFFu, p3, 16) * RSC;
        if (lane == 0) {
            g_logit[idx + 0] = make_float2(a00, a01);
            g_logit[idx + 1] = make_float2(a10, a11);
            g_logit[idx + 2] = make_float2(a20, a21);
            g_logit[idx + 3] = make_float2(a30, a31);
        }
        m0 = fmaxf(m0, fmaxf(fmaxf(a00, a10), fmaxf(a20, a30)));
        m1 = fmaxf(m1, fmaxf(fmaxf(a01, a11), fmaxf(a21, a31)));
    }
    for (; idx < end; idx++) {
        int src = __ldg(&g_esrc[idx]);
        float p;
        if (L == 2) {
            float4 ka = *(const float4*)(k + (size_t)src * 128 + lane * 4);
            p = qa4.x * ka.x + qa4.y * ka.y + qa4.z * ka.z + qa4.w * ka.w;
        } else {
            float2 ka = *(const float2*)(k + (size_t)src * 64 + lane * 2);
            p = qa2.x * ka.x + qa2.y * ka.y;
        }
#pragma unroll
        for (int d = 8; d >= 1; d >>= 1) p += __shfl_xor_sync(0xFFFFFFFFu, p, d);
        float l0 = __shfl_sync(0xFFFFFFFFu, p, 0) * RSC;
        float l1 = __shfl_sync(0xFFFFFFFFu, p, 16) * RSC;
        if (lane == 0) g_logit[idx] = make_float2(l0, l1);
        m0 = fmaxf(m0, l0);
        m1 = fmaxf(m1, l1);
    }

    // sums (coalesced re-read of just-written logits; L2-hot)
    float s0 = 0.0f, s1 = 0.0f;
    for (int base = beg; base < end; base += 32) {
        int i = base + lane;
        if (i < end) {
            float2 l = g_logit[i];
            s0 += __expf(l.x - m0);
            s1 += __expf(l.y - m1);
        }
    }
#pragma unroll
    for (int d = 16; d >= 1; d >>= 1) {
        s0 += __shfl_xor_sync(0xFFFFFFFFu, s0, d);
        s1 += __shfl_xor_sync(0xFFFFFFFFu, s1, d);
    }
    if (lane == 0) g_msum[n] = make_float4(m0, m1, s0, s1);
}

// ================= E2: weighted gather + normalize + skip + relu ===========
// 4-edge software pipelining, dual accumulators.
template <int L>
__global__ void k_e2() {
    const float* __restrict__ v    = (L == 1) ? g_v1 : g_v2;
    const float* __restrict__ skip = (L == 1) ? g_s1 : g_s2;
    float* __restrict__ outp       = (L == 1) ? g_h1 : g_q2;   // q2 reused as h2

    int n = (blockIdx.x * blockDim.x + threadIdx.x) >> 5;
    int lane = threadIdx.x & 31;
    if (n >= N_NODES) return;

    int beg = __ldg(&g_rowptr[n]);
    int end = __ldg(&g_rowptr[n + 1]);

    float4 ms = g_msum[n];
    int h = lane >> 4;
    float mh = h ? ms.y : ms.x;
    float rh = 1.0f / ((h ? ms.w : ms.z) + EPSV);

    if (L == 2) {
        float4 accA = make_float4(0.f, 0.f, 0.f, 0.f);
        float4 accB = make_float4(0.f, 0.f, 0.f, 0.f);
        int idx = beg;
        for (; idx + 4 <= end; idx += 4) {
            int s0 = __ldg(&g_esrc[idx + 0]);
            int s1 = __ldg(&g_esrc[idx + 1]);
            int s2 = __ldg(&g_esrc[idx + 2]);
            int s3 = __ldg(&g_esrc[idx + 3]);
            float2 l0 = g_logit[idx + 0];
            float2 l1 = g_logit[idx + 1];
            float2 l2 = g_logit[idx + 2];
            float2 l3 = g_logit[idx + 3];
            float4 v0 = *(const float4*)(v + (size_t)s0 * 128 + lane * 4);
            float4 v1 = *(const float4*)(v + (size_t)s1 * 128 + lane * 4);
            float4 v2 = *(const float4*)(v + (size_t)s2 * 128 + lane * 4);
            float4 v3 = *(const float4*)(v + (size_t)s3 * 128 + lane * 4);
            float e0 = __expf((h ? l0.y : l0.x) - mh);
            float e1 = __expf((h ? l1.y : l1.x) - mh);
            float e2 = __expf((h ? l2.y : l2.x) - mh);
            float e3 = __expf((h ? l3.y : l3.x) - mh);
            accA.x += e0 * v0.x + e2 * v2.x; accA.y += e0 * v0.y + e2 * v2.y;
            accA.z += e0 * v0.z + e2 * v2.z; accA.w += e0 * v0.w + e2 * v2.w;
            accB.x += e1 * v1.x + e3 * v3.x; accB.y += e1 * v1.y + e3 * v3.y;
            accB.z += e1 * v1.z + e3 * v3.z; accB.w += e1 * v1.w + e3 * v3.w;
        }
        for (; idx < end; idx++) {
            int src = __ldg(&g_esrc[idx]);
            float2 l = g_logit[idx];
            float eh = __expf((h ? l.y : l.x) - mh);
            float4 va = *(const float4*)(v + (size_t)src * 128 + lane * 4);
            accA.x += eh * va.x; accA.y += eh * va.y;
            accA.z += eh * va.z; accA.w += eh * va.w;
        }
        float4 sk = *(const float4*)(skip + (size_t)n * 128 + lane * 4);
        float4 o;
        o.x = fmaxf((accA.x + accB.x) * rh + sk.x, 0.0f);
        o.y = fmaxf((accA.y + accB.y) * rh + sk.y, 0.0f);
        o.z = fmaxf((accA.z + accB.z) * rh + sk.z, 0.0f);
        o.w = fmaxf((accA.w + accB.w) * rh + sk.w, 0.0f);
        *(float4*)(outp + (size_t)n * 128 + lane * 4) = o;
    } else {
        float2 accA = make_float2(0.f, 0.f);
        float2 accB = make_float2(0.f, 0.f);
        int idx = beg;
        for (; idx + 4 <= end; idx += 4) {
            int s0 = __ldg(&g_esrc[idx + 0]);
            int s1 = __ldg(&g_esrc[idx + 1]);
            int s2 = __ldg(&g_esrc[idx + 2]);
            int s3 = __ldg(&g_esrc[idx + 3]);
            float2 l0 = g_logit[idx + 0];
            float2 l1 = g_logit[idx + 1];
            float2 l2 = g_logit[idx + 2];
            float2 l3 = g_logit[idx + 3];
            float2 v0 = *(const float2*)(v + (size_t)s0 * 64 + lane * 2);
            float2 v1 = *(const float2*)(v + (size_t)s1 * 64 + lane * 2);
            float2 v2 = *(const float2*)(v + (size_t)s2 * 64 + lane * 2);
            float2 v3 = *(const float2*)(v + (size_t)s3 * 64 + lane * 2);
            float e0 = __expf((h ? l0.y : l0.x) - mh);
            float e1 = __expf((h ? l1.y : l1.x) - mh);
            float e2 = __expf((h ? l2.y : l2.x) - mh);
            float e3 = __expf((h ? l3.y : l3.x) - mh);
            accA.x += e0 * v0.x + e2 * v2.x; accA.y += e0 * v0.y + e2 * v2.y;
            accB.x += e1 * v1.x + e3 * v3.x; accB.y += e1 * v1.y + e3 * v3.y;
        }
        for (; idx < end; idx++) {
            int src = __ldg(&g_esrc[idx]);
            float2 l = g_logit[idx];
            float eh = __expf((h ? l.y : l.x) - mh);
            float2 va = *(const float2*)(v + (size_t)src * 64 + lane * 2);
            accA.x += eh * va.x; accA.y += eh * va.y;
        }
        float2 sk = *(const float2*)(skip + (size_t)n * 64 + lane * 2);
        float2 o;
        o.x = fmaxf((accA.x + accB.x) * rh + sk.x, 0.0f);
        o.y = fmaxf((accA.y + accB.y) * rh + sk.y, 0.0f);
        *(float2*)(outp + (size_t)n * 64 + lane * 2) = o;
    }
}

// ---------------- layer 2: node QKV + skip (register-blocked GEMM) --------
__global__ void k_l2_qkv(const float* __restrict__ Wq, const float* __restrict__ bq,
                         const float* __restrict__ Wk, const float* __restrict__ bk,
                         const float* __restrict__ Wv, const float* __restrict__ bv,
                         const float* __restrict__ Ws, const float* __restrict__ bs) {
    int j = threadIdx.x;
    int mat = blockIdx.y;
    const float* W; const float* B; float* O;
    if (mat == 0)      { W = Wq; B = bq; O = g_q2; }
    else if (mat == 1) { W = Wk; B = bk; O = g_k2; }
    else if (mat == 2) { W = Wv; B = bv; O = g_v2; }
    else               { W = Ws; B = bs; O = g_s2; }

    int nb = blockIdx.x * 8;
    float a[8];
    float bj = __ldg(B + j);
#pragma unroll
    for (int r = 0; r < 8; r++) a[r] = bj;

    for (int i = 0; i < 64; i++) {
        float w = __ldg(W + i * 128 + j);
#pragma unroll
        for (int r = 0; r < 8; r++)
            a[r] += __ldg(&g_h1[(size_t)(nb + r) * 64 + i]) * w;
    }
#pragma unroll
    for (int r = 0; r < 8; r++) O[(size_t)(nb + r) * 128 + j] = a[r];
}

// ---------------- pool init ----------------
__global__ void k_init_pool() {
    int i = blockIdx.x * blockDim.x + threadIdx.x;
    if (i < N_GRAPHS * 128) g_pool[i] = -CUDART_INF_F;
}

// ---------------- pool: run-length max over sorted batch (32 nodes/block) --
__global__ void k_pool(const int* __restrict__ batch) {
    int j = threadIdx.x;
    int n0 = blockIdx.x * 32;
    float cur = -CUDART_INF_F;
    int curg = __ldg(batch + n0);
#pragma unroll 4
    for (int r = 0; r < 32; r++) {
        int n = n0 + r;
        int g = __ldg(batch + n);
        if (g != curg) {
            atomicMaxF(&g_pool[curg * 128 + j], cur);
            cur = -CUDART_INF_F;
            curg = g;
        }
        cur = fmaxf(cur, g_q2[(size_t)n * 128 + j]);   // h2 lives in g_q2
    }
    atomicMaxF(&g_pool[curg * 128 + j], cur);
}

// ---------------- MLP head (single block) ----------------
__global__ void k_mlp(const float* __restrict__ W1, const float* __restrict__ b1,
                      const float* __restrict__ W2, const float* __restrict__ b2,
                      const float* __restrict__ W3, const float* __restrict__ b3,
                      float* __restrict__ out) {
    __shared__ float s_lat[64 * 32];
    __shared__ float s_h[64 * 128];
    int tid = threadIdx.x;
    for (int idx = tid; idx < 64 * 32; idx += blockDim.x) {
        int g = idx >> 5, j = idx & 31;
        float a = __ldg(b1 + j);
        for (int i = 0; i < 128; i++) a += g_pool[g * 128 + i] * __ldg(W1 + i * 32 + j);
        a = fmaxf(a, 0.0f);
        s_lat[idx] = a;
        out[2560 + idx] = a;
    }
    __syncthreads();
    for (int idx = tid; idx < 64 * 128; idx += blockDim.x) {
        int g = idx >> 7, j = idx & 127;
        float a = __ldg(b2 + j);
        for (int i = 0; i < 32; i++) a += s_lat[g * 32 + i] * __ldg(W2 + i * 128 + j);
        s_h[idx] = fmaxf(a, 0.0f);
    }
    __syncthreads();
    for (int idx = tid; idx < 64 * 40; idx += blockDim.x) {
        int g = idx / 40, c = idx - g * 40;
        float a = __ldg(b3 + c);
        for (int i = 0; i < 128; i++) a += s_h[g * 128 + i] * __ldg(W3 + i * 40 + c);
        out[idx] = a;
    }
}

// ---------------- launch ----------------
extern "C" void kernel_launch(void* const* d_in, const int* in_sizes, int n_in,
                              void* d_out, int out_size) {
    const float* x     = (const float*)d_in[0];
    const int*   ei    = (const int*)d_in[1];
    const int*   batch = (const int*)d_in[2];
    const float *Wq1 = (const float*)d_in[3],  *bq1 = (const float*)d_in[4];
    const float *Wk1 = (const float*)d_in[5],  *bk1 = (const float*)d_in[6];
    const float *Wv1 = (const float*)d_in[7],  *bv1 = (const float*)d_in[8];
    const float *Ws1 = (const float*)d_in[9],  *bs1 = (const float*)d_in[10];
    const float *Wq2 = (const float*)d_in[11], *bq2 = (const float*)d_in[12];
    const float *Wk2 = (const float*)d_in[13], *bk2 = (const float*)d_in[14];
    const float *Wv2 = (const float*)d_in[15], *bv2 = (const float*)d_in[16];
    const float *Ws2 = (const float*)d_in[17], *bs2 = (const float*)d_in[18];
    const float *W1  = (const float*)d_in[19], *b1  = (const float*)d_in[20];
    const float *W2  = (const float*)d_in[21], *b2  = (const float*)d_in[22];
    const float *W3  = (const float*)d_in[23], *b3  = (const float*)d_in[24];
    float* out = (float*)d_out;

    const int NODE_WARP_BLOCKS = (N_NODES * 32 + 255) / 256;

    // CSR build (once; reused by both layers)
    k_zero_deg<<<(N_NODES + 255) / 256, 256>>>();
    k_hist<<<(N_EDGES + 255) / 256, 256>>>(ei);
    k_scan<<<1, 1024>>>();
    k_scatter<<<(N_EDGES + 255) / 256, 256>>>(ei);

    // layer 1
    k_l1_qkv<<<(N_NODES * 64 + 255) / 256, 256>>>(x, Wq1, bq1, Wk1, bk1, Wv1, bv1, Ws1, bs1);
    k_init_pool<<<(N_GRAPHS * 128 + 255) / 256, 256>>>();
    k_e1<1><<<NODE_WARP_BLOCKS, 256>>>();
    k_e2<1><<<NODE_WARP_BLOCKS, 256>>>();

    // layer 2
    k_l2_qkv<<<dim3(N_NODES / 8, 4), 128>>>(Wq2, bq2, Wk2, bk2, Wv2, bv2, Ws2, bs2);
    k_e1<2><<<NODE_WARP_BLOCKS, 256>>>();
    k_e2<2><<<NODE_WARP_BLOCKS, 256>>>();
    k_pool<<<N_NODES / 32, 128>>>(batch);

    // head
    k_mlp<<<1, 256>>>(W1, b1, W2, b2, W3, b3, out);
}

// round 6
// speedup vs baseline: 2.1698x; 1.4829x over previous
#include <cuda_runtime.h>
#include <math_constants.h>

#define N_NODES 100000
#define N_EDGES 1600000
#define N_GRAPHS 64
#define EPSV 1e-16f

// ---------------- scratch (device globals; no allocations) ----------------
__device__ float g_q1[N_NODES * 64];
__device__ float g_k1[N_NODES * 64];
__device__ float g_v1[N_NODES * 64];
__device__ float g_s1[N_NODES * 64];
__device__ float g_h1[N_NODES * 64];

__device__ float g_q2[N_NODES * 128];   // after layer-2 edge pass, holds h2
__device__ float g_k2[N_NODES * 128];
__device__ float g_v2[N_NODES * 128];
__device__ float g_s2[N_NODES * 128];

__device__ float g_pool[N_GRAPHS * 128];

// CSR
__device__ int g_deg[N_NODES];
__device__ int g_rowptr[N_NODES + 1];
__device__ int g_cursor[N_NODES];
__device__ int g_esrc[N_EDGES];

// ---------------- helpers ----------------
__device__ __forceinline__ void atomicMaxF(float* addr, float val) {
    if (val >= 0.0f)
        atomicMax((int*)addr, __float_as_int(val));
    else
        atomicMin((unsigned int*)addr, __float_as_uint(val));
}

__device__ __forceinline__ unsigned long long pack_f2(float a, float b) {
    unsigned long long r;
    asm("mov.b64 %0, {%1, %2};" : "=l"(r) : "f"(a), "f"(b));
    return r;
}
__device__ __forceinline__ void ffma2(unsigned long long& d,
                                      unsigned long long a, unsigned long long b) {
    asm("fma.rn.f32x2 %0, %1, %2, %0;" : "+l"(d) : "l"(a), "l"(b));
}
__device__ __forceinline__ void unpack_f2(unsigned long long d, float& x, float& y) {
    asm("mov.b64 {%0, %1}, %2;" : "=f"(x), "=f"(y) : "l"(d));
}

// ================= CSR build =================
__global__ void k_zero_deg() {
    int i = blockIdx.x * blockDim.x + threadIdx.x;
    if (i < N_NODES) g_deg[i] = 0;
}

__global__ void k_hist(const int* __restrict__ ei) {
    int e = blockIdx.x * blockDim.x + threadIdx.x;
    if (e < N_EDGES) atomicAdd(&g_deg[__ldg(ei + N_EDGES + e)], 1);
}

__global__ void k_scan() {
    __shared__ int s_sums[1024];
    const int CH = 98;
    int t = threadIdx.x;
    int base = t * CH;
    int sum = 0;
    for (int i = 0; i < CH; i++) {
        int idx = base + i;
        if (idx < N_NODES) sum += g_deg[idx];
    }
    s_sums[t] = sum;
    __syncthreads();
    for (int d = 1; d < 1024; d <<= 1) {
        int v = (t >= d) ? s_sums[t - d] : 0;
        __syncthreads();
        s_sums[t] += v;
        __syncthreads();
    }
    int run = s_sums[t] - sum;
    for (int i = 0; i < CH; i++) {
        int idx = base + i;
        if (idx < N_NODES) {
            g_rowptr[idx] = run;
            g_cursor[idx] = run;
            run += g_deg[idx];
        }
    }
    if (t == 1023) g_rowptr[N_NODES] = N_EDGES;
}

__global__ void k_scatter(const int* __restrict__ ei) {
    int e = blockIdx.x * blockDim.x + threadIdx.x;
    if (e >= N_EDGES) return;
    int s = __ldg(ei + e);
    int d = __ldg(ei + N_EDGES + e);
    int pos = atomicAdd(&g_cursor[d], 1);
    g_esrc[pos] = s;
}

// ---------------- layer 1: node QKV + skip ----------------
__global__ void k_l1_qkv(const float* __restrict__ x,
                         const float* __restrict__ Wq, const float* __restrict__ bq,
                         const float* __restrict__ Wk, const float* __restrict__ bk,
                         const float* __restrict__ Wv, const float* __restrict__ bv,
                         const float* __restrict__ Ws, const float* __restrict__ bs) {
    int idx = blockIdx.x * blockDim.x + threadIdx.x;
    if (idx >= N_NODES * 64) return;
    int n = idx >> 6;
    int j = idx & 63;
    float x0 = __ldg(x + n * 3 + 0);
    float x1 = __ldg(x + n * 3 + 1);
    float x2 = __ldg(x + n * 3 + 2);

    g_q1[idx] = __ldg(bq + j) + x0 * __ldg(Wq + j) + x1 * __ldg(Wq + 64 + j) + x2 * __ldg(Wq + 128 + j);
    g_k1[idx] = __ldg(bk + j) + x0 * __ldg(Wk + j) + x1 * __ldg(Wk + 64 + j) + x2 * __ldg(Wk + 128 + j);
    g_v1[idx] = __ldg(bv + j) + x0 * __ldg(Wv + j) + x1 * __ldg(Wv + 64 + j) + x2 * __ldg(Wv + 128 + j);
    g_s1[idx] = __ldg(bs + j) + x0 * __ldg(Ws + j) + x1 * __ldg(Ws + 64 + j) + x2 * __ldg(Ws + 128 + j);
}

// ================= fused edge pass: logits+softmax+aggregate (warp/node) ===
// No max-shift: alpha = e^l / sum(e^l) is mathematically identical; logits O(1).
// After xor-reduce {8,4,2,1}, every lane holds its own 16-lane-group (= head) sum.
template <int L>
__global__ void k_edge() {
    constexpr float RSC = (L == 1) ? 0.17677669529663687f : 0.125f;
    const float* __restrict__ q    = (L == 1) ? g_q1 : g_q2;
    const float* __restrict__ k    = (L == 1) ? g_k1 : g_k2;
    const float* __restrict__ v    = (L == 1) ? g_v1 : g_v2;
    const float* __restrict__ skip = (L == 1) ? g_s1 : g_s2;
    float* __restrict__ outp       = (L == 1) ? g_h1 : g_q2;   // q2 reused as h2

    int n = (blockIdx.x * blockDim.x + threadIdx.x) >> 5;
    int lane = threadIdx.x & 31;
    if (n >= N_NODES) return;

    int beg = __ldg(&g_rowptr[n]);
    int end = __ldg(&g_rowptr[n + 1]);

    if (L == 2) {
        float4 qa = *(const float4*)(q + (size_t)n * 128 + lane * 4);
        float4 acc = make_float4(0.f, 0.f, 0.f, 0.f);
        float ssum = 0.0f;
        int idx = beg;
        for (; idx + 2 <= end; idx += 2) {
            int s0 = __ldg(&g_esrc[idx]);
            int s1 = __ldg(&g_esrc[idx + 1]);
            float4 k0 = *(const float4*)(k + (size_t)s0 * 128 + lane * 4);
            float4 k1 = *(const float4*)(k + (size_t)s1 * 128 + lane * 4);
            float4 v0 = *(const float4*)(v + (size_t)s0 * 128 + lane * 4);
            float4 v1 = *(const float4*)(v + (size_t)s1 * 128 + lane * 4);
            float p0 = qa.x * k0.x + qa.y * k0.y + qa.z * k0.z + qa.w * k0.w;
            float p1 = qa.x * k1.x + qa.y * k1.y + qa.z * k1.z + qa.w * k1.w;
#pragma unroll
            for (int d = 8; d >= 1; d >>= 1) {
                p0 += __shfl_xor_sync(0xFFFFFFFFu, p0, d);
                p1 += __shfl_xor_sync(0xFFFFFFFFu, p1, d);
            }
            float e0 = __expf(p0 * RSC);
            float e1 = __expf(p1 * RSC);
            ssum += e0 + e1;
            acc.x += e0 * v0.x + e1 * v1.x;
            acc.y += e0 * v0.y + e1 * v1.y;
            acc.z += e0 * v0.z + e1 * v1.z;
            acc.w += e0 * v0.w + e1 * v1.w;
        }
        for (; idx < end; idx++) {
            int s0 = __ldg(&g_esrc[idx]);
            float4 k0 = *(const float4*)(k + (size_t)s0 * 128 + lane * 4);
            float4 v0 = *(const float4*)(v + (size_t)s0 * 128 + lane * 4);
            float p0 = qa.x * k0.x + qa.y * k0.y + qa.z * k0.z + qa.w * k0.w;
#pragma unroll
            for (int d = 8; d >= 1; d >>= 1) p0 += __shfl_xor_sync(0xFFFFFFFFu, p0, d);
            float e0 = __expf(p0 * RSC);
            ssum += e0;
            acc.x += e0 * v0.x; acc.y += e0 * v0.y;
            acc.z += e0 * v0.z; acc.w += e0 * v0.w;
        }
        float rh = 1.0f / (ssum + EPSV);
        float4 sk = *(const float4*)(skip + (size_t)n * 128 + lane * 4);
        float4 o;
        o.x = fmaxf(acc.x * rh + sk.x, 0.0f);
        o.y = fmaxf(acc.y * rh + sk.y, 0.0f);
        o.z = fmaxf(acc.z * rh + sk.z, 0.0f);
        o.w = fmaxf(acc.w * rh + sk.w, 0.0f);
        *(float4*)(outp + (size_t)n * 128 + lane * 4) = o;
    } else {
        float2 qa = *(const float2*)(q + (size_t)n * 64 + lane * 2);
        float2 acc = make_float2(0.f, 0.f);
        float ssum = 0.0f;
        int idx = beg;
        for (; idx + 2 <= end; idx += 2) {
            int s0 = __ldg(&g_esrc[idx]);
            int s1 = __ldg(&g_esrc[idx + 1]);
            float2 k0 = *(const float2*)(k + (size_t)s0 * 64 + lane * 2);
            float2 k1 = *(const float2*)(k + (size_t)s1 * 64 + lane * 2);
            float2 v0 = *(const float2*)(v + (size_t)s0 * 64 + lane * 2);
            float2 v1 = *(const float2*)(v + (size_t)s1 * 64 + lane * 2);
            float p0 = qa.x * k0.x + qa.y * k0.y;
            float p1 = qa.x * k1.x + qa.y * k1.y;
#pragma unroll
            for (int d = 8; d >= 1; d >>= 1) {
                p0 += __shfl_xor_sync(0xFFFFFFFFu, p0, d);
                p1 += __shfl_xor_sync(0xFFFFFFFFu, p1, d);
            }
            float e0 = __expf(p0 * RSC);
            float e1 = __expf(p1 * RSC);
            ssum += e0 + e1;
            acc.x += e0 * v0.x + e1 * v1.x;
            acc.y += e0 * v0.y + e1 * v1.y;
        }
        for (; idx < end; idx++) {
            int s0 = __ldg(&g_esrc[idx]);
            float2 k0 = *(const float2*)(k + (size_t)s0 * 64 + lane * 2);
            float2 v0 = *(const float2*)(v + (size_t)s0 * 64 + lane * 2);
            float p0 = qa.x * k0.x + qa.y * k0.y;
#pragma unroll
            for (int d = 8; d >= 1; d >>= 1) p0 += __shfl_xor_sync(0xFFFFFFFFu, p0, d);
            float e0 = __expf(p0 * RSC);
            ssum += e0;
            acc.x += e0 * v0.x; acc.y += e0 * v0.y;
        }
        float rh = 1.0f / (ssum + EPSV);
        float2 sk = *(const float2*)(skip + (size_t)n * 64 + lane * 2);
        float2 o;
        o.x = fmaxf(acc.x * rh + sk.x, 0.0f);
        o.y = fmaxf(acc.y * rh + sk.y, 0.0f);
        *(float2*)(outp + (size_t)n * 64 + lane * 2) = o;
    }
}

// ---------------- layer 2 GEMM: f32x2 packed, smem-staged h1 ----------------
// grid (N_NODES/16, 2), block 256. Each block: 16 nodes, 2 matrices.
// smem holds h1 tile TRANSPOSED: shT[i][node], stride 20 floats (16B aligned rows).
__global__ void k_l2_qkv(const float* __restrict__ Wq, const float* __restrict__ bq,
                         const float* __restrict__ Wk, const float* __restrict__ bk,
                         const float* __restrict__ Wv, const float* __restrict__ bv,
                         const float* __restrict__ Ws, const float* __restrict__ bs) {
    __shared__ float shT[64][20];
    int tid = threadIdx.x;
    int nb = blockIdx.x * 16;

    // cooperative transpose-load: 256 threads x float4 = 1024 floats
    {
        float4 f = *(const float4*)(g_h1 + (size_t)nb * 64 + tid * 4);
        int node = tid >> 4;            // tid*4/64
        int i0 = (tid & 15) * 4;
        shT[i0 + 0][node] = f.x;
        shT[i0 + 1][node] = f.y;
        shT[i0 + 2][node] = f.z;
        shT[i0 + 3][node] = f.w;
    }
    __syncthreads();

    int mat = blockIdx.y * 2 + (tid >> 7);   // 0..3
    int j = tid & 127;
    const float* W; const float* B; float* O;
    if (mat == 0)      { W = Wq; B = bq; O = g_q2; }
    else if (mat == 1) { W = Wk; B = bk; O = g_k2; }
    else if (mat == 2) { W = Wv; B = bv; O = g_v2; }
    else               { W = Ws; B = bs; O = g_s2; }

    float bj = __ldg(B + j);
    unsigned long long acc[8];
#pragma unroll
    for (int r = 0; r < 8; r++) acc[r] = pack_f2(bj, bj);

    for (int i = 0; i < 64; i++) {
        float w = __ldg(W + i * 128 + j);
        unsigned long long wp = pack_f2(w, w);
#pragma unroll
        for (int r4 = 0; r4 < 4; r4++) {
            float4 h4 = *(const float4*)&shT[i][r4 * 4];
            unsigned long long hp0 = pack_f2(h4.x, h4.y);
            unsigned long long hp1 = pack_f2(h4.z, h4.w);
            ffma2(acc[2 * r4 + 0], hp0, wp);
            ffma2(acc[2 * r4 + 1], hp1, wp);
        }
    }
#pragma unroll
    for (int r = 0; r < 8; r++) {
        float o0, o1;
        unpack_f2(acc[r], o0, o1);
        O[(size_t)(nb + 2 * r + 0) * 128 + j] = o0;
        O[(size_t)(nb + 2 * r + 1) * 128 + j] = o1;
    }
}

// ---------------- pool init ----------------
__global__ void k_init_pool() {
    int i = blockIdx.x * blockDim.x + threadIdx.x;
    if (i < N_GRAPHS * 128) g_pool[i] = -CUDART_INF_F;
}

// ---------------- pool: run-length max over sorted batch (32 nodes/block) --
__global__ void k_pool(const int* __restrict__ batch) {
    int j = threadIdx.x;
    int n0 = blockIdx.x * 32;
    float cur = -CUDART_INF_F;
    int curg = __ldg(batch + n0);
#pragma unroll 4
    for (int r = 0; r < 32; r++) {
        int n = n0 + r;
        int g = __ldg(batch + n);
        if (g != curg) {
            atomicMaxF(&g_pool[curg * 128 + j], cur);
            cur = -CUDART_INF_F;
            curg = g;
        }
        cur = fmaxf(cur, g_q2[(size_t)n * 128 + j]);   // h2 lives in g_q2
    }
    atomicMaxF(&g_pool[curg * 128 + j], cur);
}

// ---------------- MLP head (single block) ----------------
__global__ void k_mlp(const float* __restrict__ W1, const float* __restrict__ b1,
                      const float* __restrict__ W2, const float* __restrict__ b2,
                      const float* __restrict__ W3, const float* __restrict__ b3,
                      float* __restrict__ out) {
    __shared__ float s_lat[64 * 32];
    __shared__ float s_h[64 * 128];
    int tid = threadIdx.x;
    for (int idx = tid; idx < 64 * 32; idx += blockDim.x) {
        int g = idx >> 5, j = idx & 31;
        float a = __ldg(b1 + j);
        for (int i = 0; i < 128; i++) a += g_pool[g * 128 + i] * __ldg(W1 + i * 32 + j);
        a = fmaxf(a, 0.0f);
        s_lat[idx] = a;
        out[2560 + idx] = a;
    }
    __syncthreads();
    for (int idx = tid; idx < 64 * 128; idx += blockDim.x) {
        int g = idx >> 7, j = idx & 127;
        float a = __ldg(b2 + j);
        for (int i = 0; i < 32; i++) a += s_lat[g * 32 + i] * __ldg(W2 + i * 128 + j);
        s_h[idx] = fmaxf(a, 0.0f);
    }
    __syncthreads();
    for (int idx = tid; idx < 64 * 40; idx += blockDim.x) {
        int g = idx / 40, c = idx - g * 40;
        float a = __ldg(b3 + c);
        for (int i = 0; i < 128; i++) a += s_h[g * 128 + i] * __ldg(W3 + i * 40 + c);
        out[idx] = a;
    }
}

// ---------------- launch ----------------
extern "C" void kernel_launch(void* const* d_in, const int* in_sizes, int n_in,
                              void* d_out, int out_size) {
    const float* x     = (const float*)d_in[0];
    const int*   ei    = (const int*)d_in[1];
    const int*   batch = (const int*)d_in[2];
    const float *Wq1 = (const float*)d_in[3],  *bq1 = (const float*)d_in[4];
    const float *Wk1 = (const float*)d_in[5],  *bk1 = (const float*)d_in[6];
    const float *Wv1 = (const float*)d_in[7],  *bv1 = (const float*)d_in[8];
    const float *Ws1 = (const float*)d_in[9],  *bs1 = (const float*)d_in[10];
    const float *Wq2 = (const float*)d_in[11], *bq2 = (const float*)d_in[12];
    const float *Wk2 = (const float*)d_in[13], *bk2 = (const float*)d_in[14];
    const float *Wv2 = (const float*)d_in[15], *bv2 = (const float*)d_in[16];
    const float *Ws2 = (const float*)d_in[17], *bs2 = (const float*)d_in[18];
    const float *W1  = (const float*)d_in[19], *b1  = (const float*)d_in[20];
    const float *W2  = (const float*)d_in[21], *b2  = (const float*)d_in[22];
    const float *W3  = (const float*)d_in[23], *b3  = (const float*)d_in[24];
    float* out = (float*)d_out;

    const int NODE_WARP_BLOCKS = (N_NODES * 32 + 255) / 256;

    // CSR build (once; reused by both layers)
    k_zero_deg<<<(N_NODES + 255) / 256, 256>>>();
    k_hist<<<(N_EDGES + 255) / 256, 256>>>(ei);
    k_scan<<<1, 1024>>>();
    k_scatter<<<(N_EDGES + 255) / 256, 256>>>(ei);

    // layer 1
    k_l1_qkv<<<(N_NODES * 64 + 255) / 256, 256>>>(x, Wq1, bq1, Wk1, bk1, Wv1, bv1, Ws1, bs1);
    k_init_pool<<<(N_GRAPHS * 128 + 255) / 256, 256>>>();
    k_edge<1><<<NODE_WARP_BLOCKS, 256>>>();

    // layer 2
    k_l2_qkv<<<dim3(N_NODES / 16, 2), 256>>>(Wq2, bq2, Wk2, bk2, Wv2, bv2, Ws2, bs2);
    k_edge<2><<<NODE_WARP_BLOCKS, 256>>>();
    k_pool<<<N_NODES / 32, 128>>>(batch);

    // head
    k_mlp<<<1, 256>>>(W1, b1, W2, b2, W3, b3, out);
}

// round 7
// speedup vs baseline: 2.2697x; 1.0460x over previous
#include <cuda_runtime.h>
#include <cuda_fp16.h>
#include <math_constants.h>

#define N_NODES 100000
#define N_EDGES 1600000
#define N_GRAPHS 64
#define EPSV 1e-16f

// ---------------- scratch (device globals; no allocations) ----------------
__device__ float  g_q1[N_NODES * 64];
__device__ __half g_k1h[N_NODES * 64];
__device__ __half g_v1h[N_NODES * 64];
__device__ float  g_s1[N_NODES * 64];
__device__ float  g_h1[N_NODES * 64];

__device__ float  g_q2[N_NODES * 128];   // after layer-2 edge pass, holds h2
__device__ __half g_k2h[N_NODES * 128];
__device__ __half g_v2h[N_NODES * 128];
__device__ float  g_s2[N_NODES * 128];

__device__ float g_pool[N_GRAPHS * 128];

// CSR
__device__ int g_deg[N_NODES];
__device__ int g_rowptr[N_NODES + 1];
__device__ int g_cursor[N_NODES];
__device__ int g_esrc[N_EDGES];

// ---------------- helpers ----------------
__device__ __forceinline__ void atomicMaxF(float* addr, float val) {
    if (val >= 0.0f)
        atomicMax((int*)addr, __float_as_int(val));
    else
        atomicMin((unsigned int*)addr, __float_as_uint(val));
}

__device__ __forceinline__ unsigned long long pack_f2(float a, float b) {
    unsigned long long r;
    asm("mov.b64 %0, {%1, %2};" : "=l"(r) : "f"(a), "f"(b));
    return r;
}
__device__ __forceinline__ void ffma2(unsigned long long& d,
                                      unsigned long long a, unsigned long long b) {
    asm("fma.rn.f32x2 %0, %1, %2, %0;" : "+l"(d) : "l"(a), "l"(b));
}
__device__ __forceinline__ void unpack_f2(unsigned long long d, float& x, float& y) {
    asm("mov.b64 {%0, %1}, %2;" : "=f"(x), "=f"(y) : "l"(d));
}

// load 4 halves -> float4
__device__ __forceinline__ float4 ldg_h4(const __half* p) {
    uint2 u = *(const uint2*)p;
    __half2 h0 = *reinterpret_cast<const __half2*>(&u.x);
    __half2 h1 = *reinterpret_cast<const __half2*>(&u.y);
    float2 f0 = __half22float2(h0);
    float2 f1 = __half22float2(h1);
    return make_float4(f0.x, f0.y, f1.x, f1.y);
}
// load 2 halves -> float2
__device__ __forceinline__ float2 ldg_h2(const __half* p) {
    unsigned int u = *(const unsigned int*)p;
    return __half22float2(*reinterpret_cast<const __half2*>(&u));
}

// ================= CSR build =================
__global__ void k_zero_deg() {
    int i = blockIdx.x * blockDim.x + threadIdx.x;
    if (i < N_NODES) g_deg[i] = 0;
}

// 4 edges per thread via int4
__global__ void k_hist(const int* __restrict__ ei) {
    int t = blockIdx.x * blockDim.x + threadIdx.x;
    if (t >= N_EDGES / 4) return;
    int4 d4 = __ldg((const int4*)(ei + N_EDGES) + t);
    atomicAdd(&g_deg[d4.x], 1);
    atomicAdd(&g_deg[d4.y], 1);
    atomicAdd(&g_deg[d4.z], 1);
    atomicAdd(&g_deg[d4.w], 1);
}

__global__ void k_scan() {
    __shared__ int s_sums[1024];
    const int CH = 98;
    int t = threadIdx.x;
    int base = t * CH;
    int sum = 0;
    for (int i = 0; i < CH; i++) {
        int idx = base + i;
        if (idx < N_NODES) sum += g_deg[idx];
    }
    s_sums[t] = sum;
    __syncthreads();
    for (int d = 1; d < 1024; d <<= 1) {
        int v = (t >= d) ? s_sums[t - d] : 0;
        __syncthreads();
        s_sums[t] += v;
        __syncthreads();
    }
    int run = s_sums[t] - sum;
    for (int i = 0; i < CH; i++) {
        int idx = base + i;
        if (idx < N_NODES) {
            g_rowptr[idx] = run;
            g_cursor[idx] = run;
            run += g_deg[idx];
        }
    }
    if (t == 1023) g_rowptr[N_NODES] = N_EDGES;
}

__global__ void k_scatter(const int* __restrict__ ei) {
    int t = blockIdx.x * blockDim.x + threadIdx.x;
    if (t >= N_EDGES / 4) return;
    int4 s4 = __ldg((const int4*)ei + t);
    int4 d4 = __ldg((const int4*)(ei + N_EDGES) + t);
    g_esrc[atomicAdd(&g_cursor[d4.x], 1)] = s4.x;
    g_esrc[atomicAdd(&g_cursor[d4.y], 1)] = s4.y;
    g_esrc[atomicAdd(&g_cursor[d4.z], 1)] = s4.z;
    g_esrc[atomicAdd(&g_cursor[d4.w], 1)] = s4.w;
}

// ---------------- layer 1: node QKV + skip ----------------
__global__ void k_l1_qkv(const float* __restrict__ x,
                         const float* __restrict__ Wq, const float* __restrict__ bq,
                         const float* __restrict__ Wk, const float* __restrict__ bk,
                         const float* __restrict__ Wv, const float* __restrict__ bv,
                         const float* __restrict__ Ws, const float* __restrict__ bs) {
    int idx = blockIdx.x * blockDim.x + threadIdx.x;
    if (idx >= N_NODES * 64) return;
    int n = idx >> 6;
    int j = idx & 63;
    float x0 = __ldg(x + n * 3 + 0);
    float x1 = __ldg(x + n * 3 + 1);
    float x2 = __ldg(x + n * 3 + 2);

    float q = __ldg(bq + j) + x0 * __ldg(Wq + j) + x1 * __ldg(Wq + 64 + j) + x2 * __ldg(Wq + 128 + j);
    float k = __ldg(bk + j) + x0 * __ldg(Wk + j) + x1 * __ldg(Wk + 64 + j) + x2 * __ldg(Wk + 128 + j);
    float v = __ldg(bv + j) + x0 * __ldg(Wv + j) + x1 * __ldg(Wv + 64 + j) + x2 * __ldg(Wv + 128 + j);
    float s = __ldg(bs + j) + x0 * __ldg(Ws + j) + x1 * __ldg(Ws + 64 + j) + x2 * __ldg(Ws + 128 + j);

    g_q1[idx] = q;
    g_k1h[idx] = __float2half(k);
    g_v1h[idx] = __float2half(v);
    g_s1[idx] = s;
}

// ================= fused edge pass (warp per dst node), fp16 k/v ===========
template <int L>
__global__ void k_edge() {
    constexpr float RSC = (L == 1) ? 0.17677669529663687f : 0.125f;

    int n = (blockIdx.x * blockDim.x + threadIdx.x) >> 5;
    int lane = threadIdx.x & 31;
    if (n >= N_NODES) return;

    int beg = __ldg(&g_rowptr[n]);
    int end = __ldg(&g_rowptr[n + 1]);

    if (L == 2) {
        float4 qa = *(const float4*)(g_q2 + (size_t)n * 128 + lane * 4);
        float4 acc = make_float4(0.f, 0.f, 0.f, 0.f);
        float ssum = 0.0f;
        int idx = beg;
        for (; idx + 2 <= end; idx += 2) {
            int s0 = __ldg(&g_esrc[idx]);
            int s1 = __ldg(&g_esrc[idx + 1]);
            float4 k0 = ldg_h4(g_k2h + (size_t)s0 * 128 + lane * 4);
            float4 k1 = ldg_h4(g_k2h + (size_t)s1 * 128 + lane * 4);
            float4 v0 = ldg_h4(g_v2h + (size_t)s0 * 128 + lane * 4);
            float4 v1 = ldg_h4(g_v2h + (size_t)s1 * 128 + lane * 4);
            float p0 = qa.x * k0.x + qa.y * k0.y + qa.z * k0.z + qa.w * k0.w;
            float p1 = qa.x * k1.x + qa.y * k1.y + qa.z * k1.z + qa.w * k1.w;
#pragma unroll
            for (int d = 8; d >= 1; d >>= 1) {
                p0 += __shfl_xor_sync(0xFFFFFFFFu, p0, d);
                p1 += __shfl_xor_sync(0xFFFFFFFFu, p1, d);
            }
            float e0 = __expf(p0 * RSC);
            float e1 = __expf(p1 * RSC);
            ssum += e0 + e1;
            acc.x += e0 * v0.x + e1 * v1.x;
            acc.y += e0 * v0.y + e1 * v1.y;
            acc.z += e0 * v0.z + e1 * v1.z;
            acc.w += e0 * v0.w + e1 * v1.w;
        }
        for (; idx < end; idx++) {
            int s0 = __ldg(&g_esrc[idx]);
            float4 k0 = ldg_h4(g_k2h + (size_t)s0 * 128 + lane * 4);
            float4 v0 = ldg_h4(g_v2h + (size_t)s0 * 128 + lane * 4);
            float p0 = qa.x * k0.x + qa.y * k0.y + qa.z * k0.z + qa.w * k0.w;
#pragma unroll
            for (int d = 8; d >= 1; d >>= 1) p0 += __shfl_xor_sync(0xFFFFFFFFu, p0, d);
            float e0 = __expf(p0 * RSC);
            ssum += e0;
            acc.x += e0 * v0.x; acc.y += e0 * v0.y;
            acc.z += e0 * v0.z; acc.w += e0 * v0.w;
        }
        float rh = 1.0f / (ssum + EPSV);
        float4 sk = *(const float4*)(g_s2 + (size_t)n * 128 + lane * 4);
        float4 o;
        o.x = fmaxf(acc.x * rh + sk.x, 0.0f);
        o.y = fmaxf(acc.y * rh + sk.y, 0.0f);
        o.z = fmaxf(acc.z * rh + sk.z, 0.0f);
        o.w = fmaxf(acc.w * rh + sk.w, 0.0f);
        *(float4*)(g_q2 + (size_t)n * 128 + lane * 4) = o;   // h2 in place
    } else {
        float2 qa = *(const float2*)(g_q1 + (size_t)n * 64 + lane * 2);
        float2 acc = make_float2(0.f, 0.f);
        float ssum = 0.0f;
        int idx = beg;
        for (; idx + 2 <= end; idx += 2) {
            int s0 = __ldg(&g_esrc[idx]);
            int s1 = __ldg(&g_esrc[idx + 1]);
            float2 k0 = ldg_h2(g_k1h + (size_t)s0 * 64 + lane * 2);
            float2 k1 = ldg_h2(g_k1h + (size_t)s1 * 64 + lane * 2);
            float2 v0 = ldg_h2(g_v1h + (size_t)s0 * 64 + lane * 2);
            float2 v1 = ldg_h2(g_v1h + (size_t)s1 * 64 + lane * 2);
            float p0 = qa.x * k0.x + qa.y * k0.y;
            float p1 = qa.x * k1.x + qa.y * k1.y;
#pragma unroll
            for (int d = 8; d >= 1; d >>= 1) {
                p0 += __shfl_xor_sync(0xFFFFFFFFu, p0, d);
                p1 += __shfl_xor_sync(0xFFFFFFFFu, p1, d);
            }
            float e0 = __expf(p0 * RSC);
            float e1 = __expf(p1 * RSC);
            ssum += e0 + e1;
            acc.x += e0 * v0.x + e1 * v1.x;
            acc.y += e0 * v0.y + e1 * v1.y;
        }
        for (; idx < end; idx++) {
            int s0 = __ldg(&g_esrc[idx]);
            float2 k0 = ldg_h2(g_k1h + (size_t)s0 * 64 + lane * 2);
            float2 v0 = ldg_h2(g_v1h + (size_t)s0 * 64 + lane * 2);
            float p0 = qa.x * k0.x + qa.y * k0.y;
#pragma unroll
            for (int d = 8; d >= 1; d >>= 1) p0 += __shfl_xor_sync(0xFFFFFFFFu, p0, d);
            float e0 = __expf(p0 * RSC);
            ssum += e0;
            acc.x += e0 * v0.x; acc.y += e0 * v0.y;
        }
        float rh = 1.0f / (ssum + EPSV);
        float2 sk = *(const float2*)(g_s1 + (size_t)n * 64 + lane * 2);
        float2 o;
        o.x = fmaxf(acc.x * rh + sk.x, 0.0f);
        o.y = fmaxf(acc.y * rh + sk.y, 0.0f);
        *(float2*)(g_h1 + (size_t)n * 64 + lane * 2) = o;
    }
}

// ---------------- layer 2 GEMM: f32x2 packed, smem-staged h1 ----------------
__global__ void k_l2_qkv(const float* __restrict__ Wq, const float* __restrict__ bq,
                         const float* __restrict__ Wk, const float* __restrict__ bk,
                         const float* __restrict__ Wv, const float* __restrict__ bv,
                         const float* __restrict__ Ws, const float* __restrict__ bs) {
    __shared__ float shT[64][20];
    int tid = threadIdx.x;
    int nb = blockIdx.x * 16;

    {
        float4 f = *(const float4*)(g_h1 + (size_t)nb * 64 + tid * 4);
        int node = tid >> 4;
        int i0 = (tid & 15) * 4;
        shT[i0 + 0][node] = f.x;
        shT[i0 + 1][node] = f.y;
        shT[i0 + 2][node] = f.z;
        shT[i0 + 3][node] = f.w;
    }
    __syncthreads();

    int mat = blockIdx.y * 2 + (tid >> 7);   // 0..3
    int j = tid & 127;
    const float* W; const float* B;
    float* Of = nullptr; __half* Oh = nullptr;
    if (mat == 0)      { W = Wq; B = bq; Of = g_q2; }
    else if (mat == 1) { W = Wk; B = bk; Oh = g_k2h; }
    else if (mat == 2) { W = Wv; B = bv; Oh = g_v2h; }
    else               { W = Ws; B = bs; Of = g_s2; }

    float bj = __ldg(B + j);
    unsigned long long acc[8];
#pragma unroll
    for (int r = 0; r < 8; r++) acc[r] = pack_f2(bj, bj);

    for (int i = 0; i < 64; i++) {
        float w = __ldg(W + i * 128 + j);
        unsigned long long wp = pack_f2(w, w);
#pragma unroll
        for (int r4 = 0; r4 < 4; r4++) {
            float4 h4 = *(const float4*)&shT[i][r4 * 4];
            unsigned long long hp0 = pack_f2(h4.x, h4.y);
            unsigned long long hp1 = pack_f2(h4.z, h4.w);
            ffma2(acc[2 * r4 + 0], hp0, wp);
            ffma2(acc[2 * r4 + 1], hp1, wp);
        }
    }
    if (Of) {
#pragma unroll
        for (int r = 0; r < 8; r++) {
            float o0, o1;
            unpack_f2(acc[r], o0, o1);
            Of[(size_t)(nb + 2 * r + 0) * 128 + j] = o0;
            Of[(size_t)(nb + 2 * r + 1) * 128 + j] = o1;
        }
    } else {
#pragma unroll
        for (int r = 0; r < 8; r++) {
            float o0, o1;
            unpack_f2(acc[r], o0, o1);
            Oh[(size_t)(nb + 2 * r + 0) * 128 + j] = __float2half(o0);
            Oh[(size_t)(nb + 2 * r + 1) * 128 + j] = __float2half(o1);
        }
    }
}

// ---------------- pool init ----------------
__global__ void k_init_pool() {
    int i = blockIdx.x * blockDim.x + threadIdx.x;
    if (i < N_GRAPHS * 128) g_pool[i] = -CUDART_INF_F;
}

// ---------------- pool: run-length max over sorted batch (32 nodes/block) --
__global__ void k_pool(const int* __restrict__ batch) {
    int j = threadIdx.x;
    int n0 = blockIdx.x * 32;
    float cur = -CUDART_INF_F;
    int curg = __ldg(batch + n0);
#pragma unroll 4
    for (int r = 0; r < 32; r++) {
        int n = n0 + r;
        int g = __ldg(batch + n);
        if (g != curg) {
            atomicMaxF(&g_pool[curg * 128 + j], cur);
            cur = -CUDART_INF_F;
            curg = g;
        }
        cur = fmaxf(cur, g_q2[(size_t)n * 128 + j]);   // h2 lives in g_q2
    }
    atomicMaxF(&g_pool[curg * 128 + j], cur);
}

// ---------------- MLP head (single block) ----------------
__global__ void k_mlp(const float* __restrict__ W1, const float* __restrict__ b1,
                      const float* __restrict__ W2, const float* __restrict__ b2,
                      const float* __restrict__ W3, const float* __restrict__ b3,
                      float* __restrict__ out) {
    __shared__ float s_lat[64 * 32];
    __shared__ float s_h[64 * 128];
    int tid = threadIdx.x;
    for (int idx = tid; idx < 64 * 32; idx += blockDim.x) {
        int g = idx >> 5, j = idx & 31;
        float a = __ldg(b1 + j);
        for (int i = 0; i < 128; i++) a += g_pool[g * 128 + i] * __ldg(W1 + i * 32 + j);
        a = fmaxf(a, 0.0f);
        s_lat[idx] = a;
        out[2560 + idx] = a;
    }
    __syncthreads();
    for (int idx = tid; idx < 64 * 128; idx += blockDim.x) {
        int g = idx >> 7, j = idx & 127;
        float a = __ldg(b2 + j);
        for (int i = 0; i < 32; i++) a += s_lat[g * 32 + i] * __ldg(W2 + i * 128 + j);
        s_h[idx] = fmaxf(a, 0.0f);
    }
    __syncthreads();
    for (int idx = tid; idx < 64 * 40; idx += blockDim.x) {
        int g = idx / 40, c = idx - g * 40;
        float a = __ldg(b3 + c);
        for (int i = 0; i < 128; i++) a += s_h[g * 128 + i] * __ldg(W3 + i * 40 + c);
        out[idx] = a;
    }
}

// ---------------- launch ----------------
extern "C" void kernel_launch(void* const* d_in, const int* in_sizes, int n_in,
                              void* d_out, int out_size) {
    const float* x     = (const float*)d_in[0];
    const int*   ei    = (const int*)d_in[1];
    const int*   batch = (const int*)d_in[2];
    const float *Wq1 = (const float*)d_in[3],  *bq1 = (const float*)d_in[4];
    const float *Wk1 = (const float*)d_in[5],  *bk1 = (const float*)d_in[6];
    const float *Wv1 = (const float*)d_in[7],  *bv1 = (const float*)d_in[8];
    const float *Ws1 = (const float*)d_in[9],  *bs1 = (const float*)d_in[10];
    const float *Wq2 = (const float*)d_in[11], *bq2 = (const float*)d_in[12];
    const float *Wk2 = (const float*)d_in[13], *bk2 = (const float*)d_in[14];
    const float *Wv2 = (const float*)d_in[15], *bv2 = (const float*)d_in[16];
    const float *Ws2 = (const float*)d_in[17], *bs2 = (const float*)d_in[18];
    const float *W1  = (const float*)d_in[19], *b1  = (const float*)d_in[20];
    const float *W2  = (const float*)d_in[21], *b2  = (const float*)d_in[22];
    const float *W3  = (const float*)d_in[23], *b3  = (const float*)d_in[24];
    float* out = (float*)d_out;

    const int NODE_WARP_BLOCKS = (N_NODES * 32 + 255) / 256;

    // CSR build (once; reused by both layers)
    k_zero_deg<<<(N_NODES + 255) / 256, 256>>>();
    k_hist<<<(N_EDGES / 4 + 255) / 256, 256>>>(ei);
    k_scan<<<1, 1024>>>();
    k_scatter<<<(N_EDGES / 4 + 255) / 256, 256>>>(ei);

    // layer 1
    k_l1_qkv<<<(N_NODES * 64 + 255) / 256, 256>>>(x, Wq1, bq1, Wk1, bk1, Wv1, bv1, Ws1, bs1);
    k_init_pool<<<(N_GRAPHS * 128 + 255) / 256, 256>>>();
    k_edge<1><<<NODE_WARP_BLOCKS, 256>>>();

    // layer 2
    k_l2_qkv<<<dim3(N_NODES / 16, 2), 256>>>(Wq2, bq2, Wk2, bk2, Wv2, bv2, Ws2, bs2);
    k_edge<2><<<NODE_WARP_BLOCKS, 256>>>();
    k_pool<<<N_NODES / 32, 128>>>(batch);

    // head
    k_mlp<<<1, 256>>>(W1, b1, W2, b2, W3, b3, out);
}

// round 8
// speedup vs baseline: 2.3220x; 1.0231x over previous
#include <cuda_runtime.h>
#include <cuda_fp16.h>
#include <math_constants.h>

#define N_NODES 100000
#define N_EDGES 1600000
#define N_GRAPHS 64
#define EPSV 1e-16f

// ---------------- scratch (device globals; no allocations) ----------------
__device__ float  g_q1[N_NODES * 64];
__device__ __half g_k1h[N_NODES * 64];
__device__ __half g_v1h[N_NODES * 64];
__device__ float  g_s1[N_NODES * 64];
__device__ float  g_h1[N_NODES * 64];

__device__ float  g_q2[N_NODES * 128];   // after layer-2 edge pass, holds h2
__device__ __half g_k2h[N_NODES * 128];
__device__ __half g_v2h[N_NODES * 128];
__device__ float  g_s2[N_NODES * 128];

__device__ float g_pool[N_GRAPHS * 128];

// CSR
__device__ int g_deg[N_NODES];
__device__ int g_rowptr[N_NODES + 1];
__device__ int g_cursor[N_NODES];
__device__ int g_esrc[N_EDGES];

// ---------------- helpers ----------------
__device__ __forceinline__ void atomicMaxF(float* addr, float val) {
    if (val >= 0.0f)
        atomicMax((int*)addr, __float_as_int(val));
    else
        atomicMin((unsigned int*)addr, __float_as_uint(val));
}

__device__ __forceinline__ unsigned long long pack_f2(float a, float b) {
    unsigned long long r;
    asm("mov.b64 %0, {%1, %2};" : "=l"(r) : "f"(a), "f"(b));
    return r;
}
__device__ __forceinline__ void ffma2(unsigned long long& d,
                                      unsigned long long a, unsigned long long b) {
    asm("fma.rn.f32x2 %0, %1, %2, %0;" : "+l"(d) : "l"(a), "l"(b));
}
__device__ __forceinline__ void unpack_f2(unsigned long long d, float& x, float& y) {
    asm("mov.b64 {%0, %1}, %2;" : "=f"(x), "=f"(y) : "l"(d));
}

// load 4 halves -> float4
__device__ __forceinline__ float4 ldg_h4(const __half* p) {
    uint2 u = __ldg((const uint2*)p);
    __half2 h0 = *reinterpret_cast<const __half2*>(&u.x);
    __half2 h1 = *reinterpret_cast<const __half2*>(&u.y);
    float2 f0 = __half22float2(h0);
    float2 f1 = __half22float2(h1);
    return make_float4(f0.x, f0.y, f1.x, f1.y);
}

// ================= CSR build =================
__global__ void k_zero_deg() {
    int i = blockIdx.x * blockDim.x + threadIdx.x;
    if (i < N_NODES) g_deg[i] = 0;
}

__global__ void k_hist(const int* __restrict__ ei) {
    int t = blockIdx.x * blockDim.x + threadIdx.x;
    if (t >= N_EDGES / 4) return;
    int4 d4 = __ldg((const int4*)(ei + N_EDGES) + t);
    atomicAdd(&g_deg[d4.x], 1);
    atomicAdd(&g_deg[d4.y], 1);
    atomicAdd(&g_deg[d4.z], 1);
    atomicAdd(&g_deg[d4.w], 1);
}

__global__ void k_scan() {
    __shared__ int s_sums[1024];
    const int CH = 98;
    int t = threadIdx.x;
    int base = t * CH;
    int sum = 0;
    for (int i = 0; i < CH; i++) {
        int idx = base + i;
        if (idx < N_NODES) sum += g_deg[idx];
    }
    s_sums[t] = sum;
    __syncthreads();
    for (int d = 1; d < 1024; d <<= 1) {
        int v = (t >= d) ? s_sums[t - d] : 0;
        __syncthreads();
        s_sums[t] += v;
        __syncthreads();
    }
    int run = s_sums[t] - sum;
    for (int i = 0; i < CH; i++) {
        int idx = base + i;
        if (idx < N_NODES) {
            g_rowptr[idx] = run;
            g_cursor[idx] = run;
            run += g_deg[idx];
        }
    }
    if (t == 1023) g_rowptr[N_NODES] = N_EDGES;
}

__global__ void k_scatter(const int* __restrict__ ei) {
    int t = blockIdx.x * blockDim.x + threadIdx.x;
    if (t >= N_EDGES / 4) return;
    int4 s4 = __ldg((const int4*)ei + t);
    int4 d4 = __ldg((const int4*)(ei + N_EDGES) + t);
    g_esrc[atomicAdd(&g_cursor[d4.x], 1)] = s4.x;
    g_esrc[atomicAdd(&g_cursor[d4.y], 1)] = s4.y;
    g_esrc[atomicAdd(&g_cursor[d4.z], 1)] = s4.z;
    g_esrc[atomicAdd(&g_cursor[d4.w], 1)] = s4.w;
}

// ---------------- layer 1: node QKV + skip ----------------
__global__ void k_l1_qkv(const float* __restrict__ x,
                         const float* __restrict__ Wq, const float* __restrict__ bq,
                         const float* __restrict__ Wk, const float* __restrict__ bk,
                         const float* __restrict__ Wv, const float* __restrict__ bv,
                         const float* __restrict__ Ws, const float* __restrict__ bs) {
    int idx = blockIdx.x * blockDim.x + threadIdx.x;
    if (idx >= N_NODES * 64) return;
    int n = idx >> 6;
    int j = idx & 63;
    float x0 = __ldg(x + n * 3 + 0);
    float x1 = __ldg(x + n * 3 + 1);
    float x2 = __ldg(x + n * 3 + 2);

    float q = __ldg(bq + j) + x0 * __ldg(Wq + j) + x1 * __ldg(Wq + 64 + j) + x2 * __ldg(Wq + 128 + j);
    float k = __ldg(bk + j) + x0 * __ldg(Wk + j) + x1 * __ldg(Wk + 64 + j) + x2 * __ldg(Wk + 128 + j);
    float v = __ldg(bv + j) + x0 * __ldg(Wv + j) + x1 * __ldg(Wv + 64 + j) + x2 * __ldg(Wv + 128 + j);
    float s = __ldg(bs + j) + x0 * __ldg(Ws + j) + x1 * __ldg(Ws + 64 + j) + x2 * __ldg(Ws + 128 + j);

    g_q1[idx] = q;
    g_k1h[idx] = __float2half(k);
    g_v1h[idx] = __float2half(v);
    g_s1[idx] = s;
}

// ================= layer-1 fused edge pass: 2 nodes per warp ===============
// 16 lanes per node (float4/lane over 64 cols). hl 0..7 = head0, 8..15 = head1.
__global__ void k_edge1() {
    const float RSC = 0.17677669529663687f;  // 1/sqrt(32)
    int gw = (blockIdx.x * blockDim.x + threadIdx.x) >> 5;
    int lane = threadIdx.x & 31;
    int half = lane >> 4;
    int hl = lane & 15;
    int n = gw * 2 + half;
    if (n >= N_NODES) return;                // N_NODES even -> warp uniform
    unsigned mask = half ? 0xFFFF0000u : 0x0000FFFFu;

    int beg = __ldg(&g_rowptr[n]);
    int end = __ldg(&g_rowptr[n + 1]);

    float4 qa = *(const float4*)(g_q1 + (size_t)n * 64 + hl * 4);
    float4 acc = make_float4(0.f, 0.f, 0.f, 0.f);
    float ssum = 0.0f;

    int idx = beg;
    for (; idx + 2 <= end; idx += 2) {
        int s0 = __ldg(&g_esrc[idx]);
        int s1 = __ldg(&g_esrc[idx + 1]);
        float4 k0 = ldg_h4(g_k1h + (size_t)s0 * 64 + hl * 4);
        float4 k1 = ldg_h4(g_k1h + (size_t)s1 * 64 + hl * 4);
        float4 v0 = ldg_h4(g_v1h + (size_t)s0 * 64 + hl * 4);
        float4 v1 = ldg_h4(g_v1h + (size_t)s1 * 64 + hl * 4);
        float p0 = qa.x * k0.x + qa.y * k0.y + qa.z * k0.z + qa.w * k0.w;
        float p1 = qa.x * k1.x + qa.y * k1.y + qa.z * k1.z + qa.w * k1.w;
#pragma unroll
        for (int d = 4; d >= 1; d >>= 1) {
            p0 += __shfl_xor_sync(mask, p0, d);
            p1 += __shfl_xor_sync(mask, p1, d);
        }
        float e0 = __expf(p0 * RSC);
        float e1 = __expf(p1 * RSC);
        ssum += e0 + e1;
        acc.x += e0 * v0.x + e1 * v1.x;
        acc.y += e0 * v0.y + e1 * v1.y;
        acc.z += e0 * v0.z + e1 * v1.z;
        acc.w += e0 * v0.w + e1 * v1.w;
    }
    for (; idx < end; idx++) {
        int s0 = __ldg(&g_esrc[idx]);
        float4 k0 = ldg_h4(g_k1h + (size_t)s0 * 64 + hl * 4);
        float4 v0 = ldg_h4(g_v1h + (size_t)s0 * 64 + hl * 4);
        float p0 = qa.x * k0.x + qa.y * k0.y + qa.z * k0.z + qa.w * k0.w;
#pragma unroll
        for (int d = 4; d >= 1; d >>= 1) p0 += __shfl_xor_sync(mask, p0, d);
        float e0 = __expf(p0 * RSC);
        ssum += e0;
        acc.x += e0 * v0.x; acc.y += e0 * v0.y;
        acc.z += e0 * v0.z; acc.w += e0 * v0.w;
    }
    float rh = 1.0f / (ssum + EPSV);
    float4 sk = *(const float4*)(g_s1 + (size_t)n * 64 + hl * 4);
    float4 o;
    o.x = fmaxf(acc.x * rh + sk.x, 0.0f);
    o.y = fmaxf(acc.y * rh + sk.y, 0.0f);
    o.z = fmaxf(acc.z * rh + sk.z, 0.0f);
    o.w = fmaxf(acc.w * rh + sk.w, 0.0f);
    *(float4*)(g_h1 + (size_t)n * 64 + hl * 4) = o;
}

// ================= layer-2 fused edge pass: warp/node, 4-edge batching =====
__global__ void k_edge2() {
    const float RSC = 0.125f;  // 1/sqrt(64)
    int n = (blockIdx.x * blockDim.x + threadIdx.x) >> 5;
    int lane = threadIdx.x & 31;
    if (n >= N_NODES) return;

    int beg = __ldg(&g_rowptr[n]);
    int end = __ldg(&g_rowptr[n + 1]);

    float4 qa = *(const float4*)(g_q2 + (size_t)n * 128 + lane * 4);
    float4 acc = make_float4(0.f, 0.f, 0.f, 0.f);
    float ssum = 0.0f;

    int idx = beg;
    for (; idx + 4 <= end; idx += 4) {
        int s0 = __ldg(&g_esrc[idx + 0]);
        int s1 = __ldg(&g_esrc[idx + 1]);
        int s2 = __ldg(&g_esrc[idx + 2]);
        int s3 = __ldg(&g_esrc[idx + 3]);
        float4 k0 = ldg_h4(g_k2h + (size_t)s0 * 128 + lane * 4);
        float4 k1 = ldg_h4(g_k2h + (size_t)s1 * 128 + lane * 4);
        float4 k2 = ldg_h4(g_k2h + (size_t)s2 * 128 + lane * 4);
        float4 k3 = ldg_h4(g_k2h + (size_t)s3 * 128 + lane * 4);
        float4 v0 = ldg_h4(g_v2h + (size_t)s0 * 128 + lane * 4);
        float4 v1 = ldg_h4(g_v2h + (size_t)s1 * 128 + lane * 4);
        float4 v2 = ldg_h4(g_v2h + (size_t)s2 * 128 + lane * 4);
        float4 v3 = ldg_h4(g_v2h + (size_t)s3 * 128 + lane * 4);
        float p0 = qa.x * k0.x + qa.y * k0.y + qa.z * k0.z + qa.w * k0.w;
        float p1 = qa.x * k1.x + qa.y * k1.y + qa.z * k1.z + qa.w * k1.w;
        float p2 = qa.x * k2.x + qa.y * k2.y + qa.z * k2.z + qa.w * k2.w;
        float p3 = qa.x * k3.x + qa.y * k3.y + qa.z * k3.z + qa.w * k3.w;
#pragma unroll
        for (int d = 8; d >= 1; d >>= 1) {
            p0 += __shfl_xor_sync(0xFFFFFFFFu, p0, d);
            p1 += __shfl_xor_sync(0xFFFFFFFFu, p1, d);
            p2 += __shfl_xor_sync(0xFFFFFFFFu, p2, d);
            p3 += __shfl_xor_sync(0xFFFFFFFFu, p3, d);
        }
        float e0 = __expf(p0 * RSC);
        float e1 = __expf(p1 * RSC);
        float e2 = __expf(p2 * RSC);
        float e3 = __expf(p3 * RSC);
        ssum += (e0 + e1) + (e2 + e3);
        acc.x += e0 * v0.x + e1 * v1.x + e2 * v2.x + e3 * v3.x;
        acc.y += e0 * v0.y + e1 * v1.y + e2 * v2.y + e3 * v3.y;
        acc.z += e0 * v0.z + e1 * v1.z + e2 * v2.z + e3 * v3.z;
        acc.w += e0 * v0.w + e1 * v1.w + e2 * v2.w + e3 * v3.w;
    }
    for (; idx < end; idx++) {
        int s0 = __ldg(&g_esrc[idx]);
        float4 k0 = ldg_h4(g_k2h + (size_t)s0 * 128 + lane * 4);
        float4 v0 = ldg_h4(g_v2h + (size_t)s0 * 128 + lane * 4);
        float p0 = qa.x * k0.x + qa.y * k0.y + qa.z * k0.z + qa.w * k0.w;
#pragma unroll
        for (int d = 8; d >= 1; d >>= 1) p0 += __shfl_xor_sync(0xFFFFFFFFu, p0, d);
        float e0 = __expf(p0 * RSC);
        ssum += e0;
        acc.x += e0 * v0.x; acc.y += e0 * v0.y;
        acc.z += e0 * v0.z; acc.w += e0 * v0.w;
    }
    float rh = 1.0f / (ssum + EPSV);
    float4 sk = *(const float4*)(g_s2 + (size_t)n * 128 + lane * 4);
    float4 o;
    o.x = fmaxf(acc.x * rh + sk.x, 0.0f);
    o.y = fmaxf(acc.y * rh + sk.y, 0.0f);
    o.z = fmaxf(acc.z * rh + sk.z, 0.0f);
    o.w = fmaxf(acc.w * rh + sk.w, 0.0f);
    *(float4*)(g_q2 + (size_t)n * 128 + lane * 4) = o;   // h2 in place
}

// ---------------- layer 2 GEMM: f32x2 packed, smem-staged h1 ----------------
__global__ void k_l2_qkv(const float* __restrict__ Wq, const float* __restrict__ bq,
                         const float* __restrict__ Wk, const float* __restrict__ bk,
                         const float* __restrict__ Wv, const float* __restrict__ bv,
                         const float* __restrict__ Ws, const float* __restrict__ bs) {
    __shared__ float shT[64][20];
    int tid = threadIdx.x;
    int nb = blockIdx.x * 16;

    {
        float4 f = *(const float4*)(g_h1 + (size_t)nb * 64 + tid * 4);
        int node = tid >> 4;
        int i0 = (tid & 15) * 4;
        shT[i0 + 0][node] = f.x;
        shT[i0 + 1][node] = f.y;
        shT[i0 + 2][node] = f.z;
        shT[i0 + 3][node] = f.w;
    }
    __syncthreads();

    int mat = blockIdx.y * 2 + (tid >> 7);   // 0..3
    int j = tid & 127;
    const float* W; const float* B;
    float* Of = nullptr; __half* Oh = nullptr;
    if (mat == 0)      { W = Wq; B = bq; Of = g_q2; }
    else if (mat == 1) { W = Wk; B = bk; Oh = g_k2h; }
    else if (mat == 2) { W = Wv; B = bv; Oh = g_v2h; }
    else               { W = Ws; B = bs; Of = g_s2; }

    float bj = __ldg(B + j);
    unsigned long long acc[8];
#pragma unroll
    for (int r = 0; r < 8; r++) acc[r] = pack_f2(bj, bj);

    for (int i = 0; i < 64; i++) {
        float w = __ldg(W + i * 128 + j);
        unsigned long long wp = pack_f2(w, w);
#pragma unroll
        for (int r4 = 0; r4 < 4; r4++) {
            float4 h4 = *(const float4*)&shT[i][r4 * 4];
            unsigned long long hp0 = pack_f2(h4.x, h4.y);
            unsigned long long hp1 = pack_f2(h4.z, h4.w);
            ffma2(acc[2 * r4 + 0], hp0, wp);
            ffma2(acc[2 * r4 + 1], hp1, wp);
        }
    }
    if (Of) {
#pragma unroll
        for (int r = 0; r < 8; r++) {
            float o0, o1;
            unpack_f2(acc[r], o0, o1);
            Of[(size_t)(nb + 2 * r + 0) * 128 + j] = o0;
            Of[(size_t)(nb + 2 * r + 1) * 128 + j] = o1;
        }
    } else {
#pragma unroll
        for (int r = 0; r < 8; r++) {
            float o0, o1;
            unpack_f2(acc[r], o0, o1);
            Oh[(size_t)(nb + 2 * r + 0) * 128 + j] = __float2half(o0);
            Oh[(size_t)(nb + 2 * r + 1) * 128 + j] = __float2half(o1);
        }
    }
}

// ---------------- pool init ----------------
__global__ void k_init_pool() {
    int i = blockIdx.x * blockDim.x + threadIdx.x;
    if (i < N_GRAPHS * 128) g_pool[i] = -CUDART_INF_F;
}

// ---------------- pool: run-length max over sorted batch (32 nodes/block) --
__global__ void k_pool(const int* __restrict__ batch) {
    int j = threadIdx.x;
    int n0 = blockIdx.x * 32;
    float cur = -CUDART_INF_F;
    int curg = __ldg(batch + n0);
#pragma unroll 4
    for (int r = 0; r < 32; r++) {
        int n = n0 + r;
        int g = __ldg(batch + n);
        if (g != curg) {
            atomicMaxF(&g_pool[curg * 128 + j], cur);
            cur = -CUDART_INF_F;
            curg = g;
        }
        cur = fmaxf(cur, g_q2[(size_t)n * 128 + j]);   // h2 lives in g_q2
    }
    atomicMaxF(&g_pool[curg * 128 + j], cur);
}

// ---------------- MLP head (single block) ----------------
__global__ void k_mlp(const float* __restrict__ W1, const float* __restrict__ b1,
                      const float* __restrict__ W2, const float* __restrict__ b2,
                      const float* __restrict__ W3, const float* __restrict__ b3,
                      float* __restrict__ out) {
    __shared__ float s_lat[64 * 32];
    __shared__ float s_h[64 * 128];
    int tid = threadIdx.x;
    for (int idx = tid; idx < 64 * 32; idx += blockDim.x) {
        int g = idx >> 5, j = idx & 31;
        float a = __ldg(b1 + j);
        for (int i = 0; i < 128; i++) a += g_pool[g * 128 + i] * __ldg(W1 + i * 32 + j);
        a = fmaxf(a, 0.0f);
        s_lat[idx] = a;
        out[2560 + idx] = a;
    }
    __syncthreads();
    for (int idx = tid; idx < 64 * 128; idx += blockDim.x) {
        int g = idx >> 7, j = idx & 127;
        float a = __ldg(b2 + j);
        for (int i = 0; i < 32; i++) a += s_lat[g * 32 + i] * __ldg(W2 + i * 128 + j);
        s_h[idx] = fmaxf(a, 0.0f);
    }
    __syncthreads();
    for (int idx = tid; idx < 64 * 40; idx += blockDim.x) {
        int g = idx / 40, c = idx - g * 40;
        float a = __ldg(b3 + c);
        for (int i = 0; i < 128; i++) a += s_h[g * 128 + i] * __ldg(W3 + i * 40 + c);
        out[idx] = a;
    }
}

// ---------------- launch ----------------
extern "C" void kernel_launch(void* const* d_in, const int* in_sizes, int n_in,
                              void* d_out, int out_size) {
    const float* x     = (const float*)d_in[0];
    const int*   ei    = (const int*)d_in[1];
    const int*   batch = (const int*)d_in[2];
    const float *Wq1 = (const float*)d_in[3],  *bq1 = (const float*)d_in[4];
    const float *Wk1 = (const float*)d_in[5],  *bk1 = (const float*)d_in[6];
    const float *Wv1 = (const float*)d_in[7],  *bv1 = (const float*)d_in[8];
    const float *Ws1 = (const float*)d_in[9],  *bs1 = (const float*)d_in[10];
    const float *Wq2 = (const float*)d_in[11], *bq2 = (const float*)d_in[12];
    const float *Wk2 = (const float*)d_in[13], *bk2 = (const float*)d_in[14];
    const float *Wv2 = (const float*)d_in[15], *bv2 = (const float*)d_in[16];
    const float *Ws2 = (const float*)d_in[17], *bs2 = (const float*)d_in[18];
    const float *W1  = (const float*)d_in[19], *b1  = (const float*)d_in[20];
    const float *W2  = (const float*)d_in[21], *b2  = (const float*)d_in[22];
    const float *W3  = (const float*)d_in[23], *b3  = (const float*)d_in[24];
    float* out = (float*)d_out;

    // one-time side stream + fork/join events (host-side resources only)
    static cudaStream_t s_side = nullptr;
    static cudaEvent_t ev_fork = nullptr, ev_join = nullptr;
    if (s_side == nullptr) {
        cudaStreamCreateWithFlags(&s_side, cudaStreamNonBlocking);
        cudaEventCreateWithFlags(&ev_fork, cudaEventDisableTiming);
        cudaEventCreateWithFlags(&ev_join, cudaEventDisableTiming);
    }

    const int NODE_WARP_BLOCKS = (N_NODES * 32 + 255) / 256;   // warp per node
    const int PAIR_NODE_BLOCKS = ((N_NODES / 2) * 32 + 255) / 256;  // 2 nodes/warp

    // fork: CSR build on side stream, concurrent with layer-1 QKV
    cudaEventRecord(ev_fork, 0);
    cudaStreamWaitEvent(s_side, ev_fork, 0);
    k_zero_deg<<<(N_NODES + 255) / 256, 256, 0, s_side>>>();
    k_hist<<<(N_EDGES / 4 + 255) / 256, 256, 0, s_side>>>(ei);
    k_scan<<<1, 1024, 0, s_side>>>();
    k_scatter<<<(N_EDGES / 4 + 255) / 256, 256, 0, s_side>>>(ei);
    cudaEventRecord(ev_join, s_side);

    // main stream: node-parallel work that doesn't need the CSR
    k_l1_qkv<<<(N_NODES * 64 + 255) / 256, 256>>>(x, Wq1, bq1, Wk1, bk1, Wv1, bv1, Ws1, bs1);
    k_init_pool<<<(N_GRAPHS * 128 + 255) / 256, 256>>>();

    // join
    cudaStreamWaitEvent(0, ev_join, 0);

    // layer 1 edges
    k_edge1<<<PAIR_NODE_BLOCKS, 256>>>();

    // layer 2
    k_l2_qkv<<<dim3(N_NODES / 16, 2), 256>>>(Wq2, bq2, Wk2, bk2, Wv2, bv2, Ws2, bs2);
    k_edge2<<<NODE_WARP_BLOCKS, 256>>>();
    k_pool<<<N_NODES / 32, 128>>>(batch);

    // head
    k_mlp<<<1, 256>>>(W1, b1, W2, b2, W3, b3, out);
}